// round 3
// baseline (speedup 1.0000x reference)
#include <cuda_runtime.h>
#include <cuda_bf16.h>
#include <cstdint>
#include <cstddef>

// Shapes: B=64, S=512, D=768, H=512, T=37
// Inputs: 0 word_reprs f32[64,512,768], 1 word_mask (dtype sniffed) [64,512],
//         2 labels i32[64,512], 3 W1 f32[768,512], 4 b1 f32[512],
//         5 W2 f32[512,37], 6 b2 f32[37], 7 transitions f32[37,37],
//         8 start_trans f32[37], 9 end_trans f32[37]
// Output: scalar f32 loss.

// ---------------- device scratch (no runtime allocation) ----------------
__device__ __align__(16) __nv_bfloat16 g_h[(size_t)32768 * 512];   // 32 MB hidden
__device__ __align__(16) float g_expem[(size_t)32768 * 37];        // exp(logits)
__device__ int   g_len[64];
__device__ float g_partial[64];

// ---------------- helpers ----------------
__device__ __forceinline__ void mma16816(float* d, const unsigned* a, const unsigned* b) {
    asm volatile(
        "mma.sync.aligned.m16n8k16.row.col.f32.bf16.bf16.f32 "
        "{%0,%1,%2,%3},{%4,%5,%6,%7},{%8,%9},{%0,%1,%2,%3};\n"
        : "+f"(d[0]), "+f"(d[1]), "+f"(d[2]), "+f"(d[3])
        : "r"(a[0]), "r"(a[1]), "r"(a[2]), "r"(a[3]), "r"(b[0]), "r"(b[1]));
}

// ---------------- lengths (mask dtype sniffed) ----------------
__global__ void prep_kernel(const void* __restrict__ mask) {
    __shared__ int rs[64];
    const int b = blockIdx.x, tid = threadIdx.x;
    const unsigned w0 = *(const unsigned*)mask;  // first 4 elems always true
    int cnt = 0;
    if (w0 == 0x01010101u) {                       // bool / uint8
        const unsigned char* p = (const unsigned char*)mask + (size_t)b * 512;
        for (int i = tid; i < 512; i += 64) cnt += (p[i] != 0);
    } else if (w0 == 0x3F800000u) {                // float32
        const float* p = (const float*)mask + (size_t)b * 512;
        for (int i = tid; i < 512; i += 64) cnt += (p[i] != 0.f);
    } else {                                       // int32
        const int* p = (const int*)mask + (size_t)b * 512;
        for (int i = tid; i < 512; i += 64) cnt += (p[i] != 0);
    }
    rs[tid] = cnt;
    __syncthreads();
    if (tid == 0) {
        int s = 0;
        for (int i = 0; i < 64; i++) s += rs[i];
        g_len[b] = s;
    }
}

// ---------------- GEMM1: h = relu(X@W1 + b1), bf16 mma ----------------
// X[32768,768] f32, W1[768,512] f32 -> g_h bf16 [32768,512]
// BM=128 BN=128 BK=32, 256 threads (8 warps, 4x2), warp tile 32x64.
__global__ __launch_bounds__(256) void gemm1_kernel(const float* __restrict__ X,
                                                    const float* __restrict__ W1,
                                                    const float* __restrict__ b1) {
    __shared__ __nv_bfloat16 As[128 * 40];  // [m][k] stride 40
    __shared__ __nv_bfloat16 Bs[128 * 40];  // [n][k] stride 40
    const int tid  = threadIdx.x;
    const int lane = tid & 31;
    const int wid  = tid >> 5;
    const int wm   = wid & 3;            // 0..3 -> row
    const int wn   = wid >> 2;           // 0..1 -> col
    const int m0   = blockIdx.y * 128;
    const int n0   = blockIdx.x * 128;
    const int wrow = wm * 32;
    const int wcol = wn * 64;
    const int gp   = lane >> 2;          // 0..7
    const int tg   = lane & 3;           // 0..3

    float acc[2][8][4];
#pragma unroll
    for (int i = 0; i < 2; i++)
#pragma unroll
        for (int j = 0; j < 8; j++)
#pragma unroll
            for (int k = 0; k < 4; k++) acc[i][j][k] = 0.f;

    float4 ra[4], rb[4];

    // prefetch k-tile 0
#pragma unroll
    for (int i = 0; i < 4; i++) {
        int idx = tid + i * 256;
        int r = idx >> 3, c = idx & 7;
        ra[i] = *(const float4*)(X + (size_t)(m0 + r) * 768 + c * 4);
    }
#pragma unroll
    for (int i = 0; i < 4; i++) {
        int idx = tid + i * 256;
        int kr = idx >> 5, nc = idx & 31;
        rb[i] = *(const float4*)(W1 + (size_t)kr * 512 + n0 + nc * 4);
    }

    for (int kt = 0; kt < 24; kt++) {
        __syncthreads();
        // stage A (convert f32 -> bf16)
#pragma unroll
        for (int i = 0; i < 4; i++) {
            int idx = tid + i * 256;
            int r = idx >> 3, c = idx & 7;
            __nv_bfloat162 h0 = __floats2bfloat162_rn(ra[i].x, ra[i].y);
            __nv_bfloat162 h1 = __floats2bfloat162_rn(ra[i].z, ra[i].w);
            *(__nv_bfloat162*)&As[r * 40 + c * 4]     = h0;
            *(__nv_bfloat162*)&As[r * 40 + c * 4 + 2] = h1;
        }
        // stage B transposed into [n][k]
#pragma unroll
        for (int i = 0; i < 4; i++) {
            int idx = tid + i * 256;
            int kr = idx >> 5, nc = idx & 31;
            Bs[(nc * 4 + 0) * 40 + kr] = __float2bfloat16(rb[i].x);
            Bs[(nc * 4 + 1) * 40 + kr] = __float2bfloat16(rb[i].y);
            Bs[(nc * 4 + 2) * 40 + kr] = __float2bfloat16(rb[i].z);
            Bs[(nc * 4 + 3) * 40 + kr] = __float2bfloat16(rb[i].w);
        }
        __syncthreads();
        if (kt < 23) {
            int k0 = (kt + 1) * 32;
#pragma unroll
            for (int i = 0; i < 4; i++) {
                int idx = tid + i * 256;
                int r = idx >> 3, c = idx & 7;
                ra[i] = *(const float4*)(X + (size_t)(m0 + r) * 768 + k0 + c * 4);
            }
#pragma unroll
            for (int i = 0; i < 4; i++) {
                int idx = tid + i * 256;
                int kr = idx >> 5, nc = idx & 31;
                rb[i] = *(const float4*)(W1 + (size_t)(k0 + kr) * 512 + n0 + nc * 4);
            }
        }
#pragma unroll
        for (int kk = 0; kk < 32; kk += 16) {
            unsigned af[2][4], bfr[8][2];
#pragma unroll
            for (int i = 0; i < 2; i++) {
                int r = wrow + i * 16 + gp;
                af[i][0] = *(const unsigned*)&As[r * 40 + kk + tg * 2];
                af[i][1] = *(const unsigned*)&As[(r + 8) * 40 + kk + tg * 2];
                af[i][2] = *(const unsigned*)&As[r * 40 + kk + tg * 2 + 8];
                af[i][3] = *(const unsigned*)&As[(r + 8) * 40 + kk + tg * 2 + 8];
            }
#pragma unroll
            for (int j = 0; j < 8; j++) {
                int n = wcol + j * 8 + gp;
                bfr[j][0] = *(const unsigned*)&Bs[n * 40 + kk + tg * 2];
                bfr[j][1] = *(const unsigned*)&Bs[n * 40 + kk + tg * 2 + 8];
            }
#pragma unroll
            for (int i = 0; i < 2; i++)
#pragma unroll
                for (int j = 0; j < 8; j++) mma16816(acc[i][j], af[i], bfr[j]);
        }
    }

    // epilogue: bias + relu, store bf16
#pragma unroll
    for (int i = 0; i < 2; i++) {
        int r0 = m0 + wrow + i * 16 + gp;
        int r1 = r0 + 8;
#pragma unroll
        for (int j = 0; j < 8; j++) {
            int c = n0 + wcol + j * 8 + tg * 2;
            float bia0 = b1[c], bia1 = b1[c + 1];
            float v00 = fmaxf(acc[i][j][0] + bia0, 0.f);
            float v01 = fmaxf(acc[i][j][1] + bia1, 0.f);
            float v10 = fmaxf(acc[i][j][2] + bia0, 0.f);
            float v11 = fmaxf(acc[i][j][3] + bia1, 0.f);
            *(__nv_bfloat162*)&g_h[(size_t)r0 * 512 + c] = __floats2bfloat162_rn(v00, v01);
            *(__nv_bfloat162*)&g_h[(size_t)r1 * 512 + c] = __floats2bfloat162_rn(v10, v11);
        }
    }
}

// ---------------- GEMM2: expem = exp(h@W2 + b2) ----------------
// g_h bf16 [32768,512] @ W2 f32 [512,37]. BM=128, N padded 37->40, BK=64.
// 128 threads, 4 warps; warp w handles rows w*32..w*32+31, all 5 n-tiles.
__global__ __launch_bounds__(128) void gemm2_kernel(const float* __restrict__ W2,
                                                    const float* __restrict__ b2) {
    __shared__ __nv_bfloat16 As[128 * 72];  // [m][k] stride 72
    __shared__ __nv_bfloat16 Bs[40 * 72];   // [n][k] stride 72
    const int tid  = threadIdx.x;
    const int lane = tid & 31;
    const int wid  = tid >> 5;
    const int m0   = blockIdx.x * 128;
    const int wrow = wid * 32;
    const int gp   = lane >> 2;
    const int tg   = lane & 3;

    float acc[2][5][4];
#pragma unroll
    for (int i = 0; i < 2; i++)
#pragma unroll
        for (int j = 0; j < 5; j++)
#pragma unroll
            for (int k = 0; k < 4; k++) acc[i][j][k] = 0.f;

    for (int kt = 0; kt < 8; kt++) {
        __syncthreads();
        int k0 = kt * 64;
        // A: 128x64 bf16, uint2 = 4 bf16
#pragma unroll
        for (int i = 0; i < 16; i++) {
            int idx = tid + i * 128;
            int r = idx >> 4, c = idx & 15;
            *(uint2*)&As[r * 72 + c * 4] =
                *(const uint2*)&g_h[(size_t)(m0 + r) * 512 + k0 + c * 4];
        }
        // B: W2[k0+k][n] -> Bs[n][k], zero pad n=37..39
        for (int idx = tid; idx < 40 * 64; idx += 128) {
            int k = idx & 63, n = idx >> 6;
            Bs[n * 72 + k] = (n < 37) ? __float2bfloat16(W2[(size_t)(k0 + k) * 37 + n])
                                      : __float2bfloat16(0.f);
        }
        __syncthreads();
#pragma unroll
        for (int kk = 0; kk < 64; kk += 16) {
            unsigned af[2][4], bfr[5][2];
#pragma unroll
            for (int i = 0; i < 2; i++) {
                int r = wrow + i * 16 + gp;
                af[i][0] = *(const unsigned*)&As[r * 72 + kk + tg * 2];
                af[i][1] = *(const unsigned*)&As[(r + 8) * 72 + kk + tg * 2];
                af[i][2] = *(const unsigned*)&As[r * 72 + kk + tg * 2 + 8];
                af[i][3] = *(const unsigned*)&As[(r + 8) * 72 + kk + tg * 2 + 8];
            }
#pragma unroll
            for (int j = 0; j < 5; j++) {
                int n = j * 8 + gp;
                bfr[j][0] = *(const unsigned*)&Bs[n * 72 + kk + tg * 2];
                bfr[j][1] = *(const unsigned*)&Bs[n * 72 + kk + tg * 2 + 8];
            }
#pragma unroll
            for (int i = 0; i < 2; i++)
#pragma unroll
                for (int j = 0; j < 5; j++) mma16816(acc[i][j], af[i], bfr[j]);
        }
    }

    // epilogue: bias + exp, store f32 expem
#pragma unroll
    for (int i = 0; i < 2; i++) {
        int r0 = m0 + wrow + i * 16 + gp;
        int r1 = r0 + 8;
#pragma unroll
        for (int j = 0; j < 5; j++) {
            int c = j * 8 + tg * 2;
            if (c < 37) {
                float bia = b2[c];
                g_expem[(size_t)r0 * 37 + c] = expf(acc[i][j][0] + bia);
                g_expem[(size_t)r1 * 37 + c] = expf(acc[i][j][2] + bia);
            }
            if (c + 1 < 37) {
                float bia = b2[c + 1];
                g_expem[(size_t)r0 * 37 + c + 1] = expf(acc[i][j][1] + bia);
                g_expem[(size_t)r1 * 37 + c + 1] = expf(acc[i][j][3] + bia);
            }
        }
    }
}

// ---------------- CRF: exp-domain forward + gold score ----------------
// One block per batch, 64 threads: warp0 = alpha recursion, warp1 = gold path.
__global__ __launch_bounds__(64) void crf_kernel(const float* __restrict__ trans,
                                                 const float* __restrict__ startt,
                                                 const float* __restrict__ endt,
                                                 const int* __restrict__ labels) {
    __shared__ float sa[37];
    __shared__ float sred[2];  // [0]=logZ, [1]=gold
    const int b = blockIdx.x, tid = threadIdx.x;
    const int len = g_len[b];
    const size_t base = (size_t)b * 512;
    const int* lab = labels + (size_t)b * 512;

    if (tid < 32) {
        const int t = tid;
        const int j1 = t + 32;
        const bool has2 = (t < 5);
        float E0[37], E1[37];
        for (int i = 0; i < 37; i++) {
            E0[i] = expf(trans[i * 37 + t]);
            E1[i] = has2 ? expf(trans[i * 37 + j1]) : 0.f;
        }
        const float ee0 = expf(endt[t]);
        const float ee1 = has2 ? expf(endt[j1]) : 0.f;

        float a0 = expf(startt[t]) * g_expem[base * 37 + t];
        float a1 = has2 ? expf(startt[j1]) * g_expem[base * 37 + j1] : 0.f;
        sa[t] = a0;
        if (has2) sa[j1] = a1;
        float logscale = 0.f;
        __syncwarp();

        for (int s = 1; s < len; s++) {
            float em0 = g_expem[(base + s) * 37 + t];
            float em1 = has2 ? g_expem[(base + s) * 37 + j1] : 0.f;
            float p0 = 0.f, q0 = 0.f, p1 = 0.f, q1 = 0.f;
#pragma unroll
            for (int i = 0; i < 36; i += 2) {
                float v = sa[i], w = sa[i + 1];
                p0 = fmaf(v, E0[i],     p0);
                q0 = fmaf(w, E0[i + 1], q0);
                p1 = fmaf(v, E1[i],     p1);
                q1 = fmaf(w, E1[i + 1], q1);
            }
            {
                float v = sa[36];
                p0 = fmaf(v, E0[36], p0);
                p1 = fmaf(v, E1[36], p1);
            }
            float na0 = (p0 + q0) * em0;
            float na1 = (p1 + q1) * em1;
            if ((s & 7) == 0) {  // periodic rescale keeps fp32 in range
                float mm = fmaxf(na0, na1);
#pragma unroll
                for (int off = 16; off; off >>= 1)
                    mm = fmaxf(mm, __shfl_xor_sync(0xffffffffu, mm, off));
                logscale += logf(mm);
                float inv = 1.f / mm;
                na0 *= inv;
                na1 *= inv;
            }
            __syncwarp();
            sa[t] = na0;
            if (has2) sa[j1] = na1;
            __syncwarp();
            a0 = na0;
            a1 = na1;
        }

        float z = a0 * ee0 + (has2 ? a1 * ee1 : 0.f);
#pragma unroll
        for (int off = 16; off; off >>= 1) z += __shfl_xor_sync(0xffffffffu, z, off);
        if (t == 0) sred[0] = logscale + logf(z);
    } else {
        const int k = tid - 32;
        float g = 0.f;
        for (int s = k; s < len; s += 32)
            g += logf(g_expem[(base + s) * 37 + lab[s]]);
        for (int s = 1 + k; s < len; s += 32)
            g += trans[lab[s - 1] * 37 + lab[s]];
        if (k == 0) g += startt[lab[0]] + endt[lab[len - 1]];
#pragma unroll
        for (int off = 16; off; off >>= 1) g += __shfl_xor_sync(0xffffffffu, g, off);
        if (k == 0) sred[1] = g;
    }
    __syncthreads();
    if (tid == 0) g_partial[b] = sred[0] - sred[1];
}

// ---------------- finalize: mean over batches ----------------
__global__ void finalize_kernel(float* __restrict__ out) {
    const int t = threadIdx.x;  // 32 threads
    float v = g_partial[t] + g_partial[t + 32];
#pragma unroll
    for (int off = 16; off; off >>= 1) v += __shfl_xor_sync(0xffffffffu, v, off);
    if (t == 0) out[0] = v * (1.f / 64.f);
}

// ---------------- launch ----------------
extern "C" void kernel_launch(void* const* d_in, const int* in_sizes, int n_in,
                              void* d_out, int out_size) {
    const float* X      = (const float*)d_in[0];
    const void*  mask   = d_in[1];
    const int*   labels = (const int*)d_in[2];
    const float* W1     = (const float*)d_in[3];
    const float* b1     = (const float*)d_in[4];
    const float* W2     = (const float*)d_in[5];
    const float* b2     = (const float*)d_in[6];
    const float* trans  = (const float*)d_in[7];
    const float* startt = (const float*)d_in[8];
    const float* endt   = (const float*)d_in[9];
    float* out = (float*)d_out;

    prep_kernel<<<64, 64>>>(mask);
    gemm1_kernel<<<dim3(4, 256), 256>>>(X, W1, b1);
    gemm2_kernel<<<256, 128>>>(W2, b2);
    crf_kernel<<<64, 64>>>(trans, startt, endt, labels);
    finalize_kernel<<<1, 32>>>(out);
}

// round 5
// speedup vs baseline: 1.1164x; 1.1164x over previous
#include <cuda_runtime.h>
#include <cuda_bf16.h>
#include <cstdint>
#include <cstddef>

// Shapes: B=64, S=512, D=768, H=512, T=37
// Inputs: 0 word_reprs f32[64,512,768], 1 word_mask (dtype sniffed) [64,512],
//         2 labels i32[64,512], 3 W1 f32[768,512], 4 b1 f32[512],
//         5 W2 f32[512,37], 6 b2 f32[37], 7 transitions f32[37,37],
//         8 start_trans f32[37], 9 end_trans f32[37]
// Output: scalar f32 loss.

// ---------------- device scratch (no runtime allocation) ----------------
__device__ __align__(16) __nv_bfloat16 g_h[(size_t)32768 * 512];   // 32 MB hidden
__device__ __align__(16) float g_expem[(size_t)32768 * 37];        // exp(logits)
__device__ int   g_len[64];
__device__ float g_partial[64];

// ---------------- helpers ----------------
__device__ __forceinline__ void mma16816(float* d, const unsigned* a, const unsigned* b) {
    asm volatile(
        "mma.sync.aligned.m16n8k16.row.col.f32.bf16.bf16.f32 "
        "{%0,%1,%2,%3},{%4,%5,%6,%7},{%8,%9},{%0,%1,%2,%3};\n"
        : "+f"(d[0]), "+f"(d[1]), "+f"(d[2]), "+f"(d[3])
        : "r"(a[0]), "r"(a[1]), "r"(a[2]), "r"(a[3]), "r"(b[0]), "r"(b[1]));
}

// pack two bf16x2 into a uint2 for one STS.64
__device__ __forceinline__ uint2 pack_bf16x4(float a, float b, float c, float d) {
    __nv_bfloat162 h0 = __floats2bfloat162_rn(a, b);
    __nv_bfloat162 h1 = __floats2bfloat162_rn(c, d);
    uint2 r;
    r.x = *reinterpret_cast<unsigned*>(&h0);
    r.y = *reinterpret_cast<unsigned*>(&h1);
    return r;
}

// ---------------- lengths (mask dtype sniffed) ----------------
__global__ void prep_kernel(const void* __restrict__ mask) {
    __shared__ int rs[64];
    const int b = blockIdx.x, tid = threadIdx.x;
    const unsigned w0 = *(const unsigned*)mask;  // first 4 elems always true
    int cnt = 0;
    if (w0 == 0x01010101u) {                       // bool / uint8
        const unsigned char* p = (const unsigned char*)mask + (size_t)b * 512;
        for (int i = tid; i < 512; i += 64) cnt += (p[i] != 0);
    } else if (w0 == 0x3F800000u) {                // float32
        const float* p = (const float*)mask + (size_t)b * 512;
        for (int i = tid; i < 512; i += 64) cnt += (p[i] != 0.f);
    } else {                                       // int32
        const int* p = (const int*)mask + (size_t)b * 512;
        for (int i = tid; i < 512; i += 64) cnt += (p[i] != 0);
    }
    rs[tid] = cnt;
    __syncthreads();
    if (tid == 0) {
        int s = 0;
        for (int i = 0; i < 64; i++) s += rs[i];
        g_len[b] = s;
    }
}

// ---------------- GEMM1: h = relu(X@W1 + b1), bf16 mma ----------------
// X[32768,768] f32, W1[768,512] f32 -> g_h bf16 [32768,512]
// BM=128 BN=128 BK=32, 256 threads (8 warps, 4x2), warp tile 32x64.
// Bs row stride 42: thread stride 4*42*2B = 84 words, gcd(84,32)=4
// -> 4-way STS conflict instead of 32-way.
#define BS_STRIDE 42
__global__ __launch_bounds__(256) void gemm1_kernel(const float* __restrict__ X,
                                                    const float* __restrict__ W1,
                                                    const float* __restrict__ b1) {
    __shared__ __nv_bfloat16 As[128 * 40];        // [m][k] stride 40
    __shared__ __nv_bfloat16 Bs[128 * BS_STRIDE]; // [n][k] stride 42
    const int tid  = threadIdx.x;
    const int lane = tid & 31;
    const int wid  = tid >> 5;
    const int wm   = wid & 3;            // 0..3 -> row
    const int wn   = wid >> 2;           // 0..1 -> col
    const int m0   = blockIdx.y * 128;
    const int n0   = blockIdx.x * 128;
    const int wrow = wm * 32;
    const int wcol = wn * 64;
    const int gp   = lane >> 2;          // 0..7
    const int tg   = lane & 3;           // 0..3

    float acc[2][8][4];
#pragma unroll
    for (int i = 0; i < 2; i++)
#pragma unroll
        for (int j = 0; j < 8; j++)
#pragma unroll
            for (int k = 0; k < 4; k++) acc[i][j][k] = 0.f;

    float4 ra[4], rb[4];

    // prefetch k-tile 0
#pragma unroll
    for (int i = 0; i < 4; i++) {
        int idx = tid + i * 256;
        int r = idx >> 3, c = idx & 7;
        ra[i] = *(const float4*)(X + (size_t)(m0 + r) * 768 + c * 4);
    }
#pragma unroll
    for (int i = 0; i < 4; i++) {
        int idx = tid + i * 256;
        int kr = idx >> 5, nc = idx & 31;
        rb[i] = *(const float4*)(W1 + (size_t)kr * 512 + n0 + nc * 4);
    }

    for (int kt = 0; kt < 24; kt++) {
        __syncthreads();
        // stage A (convert f32 -> bf16), one 8B store per thread-iter
#pragma unroll
        for (int i = 0; i < 4; i++) {
            int idx = tid + i * 256;
            int r = idx >> 3, c = idx & 7;
            *(uint2*)&As[r * 40 + c * 4] = pack_bf16x4(ra[i].x, ra[i].y, ra[i].z, ra[i].w);
        }
        // stage B transposed into [n][k]
#pragma unroll
        for (int i = 0; i < 4; i++) {
            int idx = tid + i * 256;
            int kr = idx >> 5, nc = idx & 31;
            Bs[(nc * 4 + 0) * BS_STRIDE + kr] = __float2bfloat16(rb[i].x);
            Bs[(nc * 4 + 1) * BS_STRIDE + kr] = __float2bfloat16(rb[i].y);
            Bs[(nc * 4 + 2) * BS_STRIDE + kr] = __float2bfloat16(rb[i].z);
            Bs[(nc * 4 + 3) * BS_STRIDE + kr] = __float2bfloat16(rb[i].w);
        }
        __syncthreads();
        if (kt < 23) {
            int k0 = (kt + 1) * 32;
#pragma unroll
            for (int i = 0; i < 4; i++) {
                int idx = tid + i * 256;
                int r = idx >> 3, c = idx & 7;
                ra[i] = *(const float4*)(X + (size_t)(m0 + r) * 768 + k0 + c * 4);
            }
#pragma unroll
            for (int i = 0; i < 4; i++) {
                int idx = tid + i * 256;
                int kr = idx >> 5, nc = idx & 31;
                rb[i] = *(const float4*)(W1 + (size_t)(k0 + kr) * 512 + n0 + nc * 4);
            }
        }
#pragma unroll
        for (int kk = 0; kk < 32; kk += 16) {
            unsigned af[2][4], bfr[8][2];
#pragma unroll
            for (int i = 0; i < 2; i++) {
                int r = wrow + i * 16 + gp;
                af[i][0] = *(const unsigned*)&As[r * 40 + kk + tg * 2];
                af[i][1] = *(const unsigned*)&As[(r + 8) * 40 + kk + tg * 2];
                af[i][2] = *(const unsigned*)&As[r * 40 + kk + tg * 2 + 8];
                af[i][3] = *(const unsigned*)&As[(r + 8) * 40 + kk + tg * 2 + 8];
            }
#pragma unroll
            for (int j = 0; j < 8; j++) {
                int n = wcol + j * 8 + gp;
                bfr[j][0] = *(const unsigned*)&Bs[n * BS_STRIDE + kk + tg * 2];
                bfr[j][1] = *(const unsigned*)&Bs[n * BS_STRIDE + kk + tg * 2 + 8];
            }
#pragma unroll
            for (int i = 0; i < 2; i++)
#pragma unroll
                for (int j = 0; j < 8; j++) mma16816(acc[i][j], af[i], bfr[j]);
        }
    }

    // epilogue: bias + relu, store bf16
#pragma unroll
    for (int i = 0; i < 2; i++) {
        int r0 = m0 + wrow + i * 16 + gp;
        int r1 = r0 + 8;
#pragma unroll
        for (int j = 0; j < 8; j++) {
            int c = n0 + wcol + j * 8 + tg * 2;
            float bia0 = b1[c], bia1 = b1[c + 1];
            float v00 = fmaxf(acc[i][j][0] + bia0, 0.f);
            float v01 = fmaxf(acc[i][j][1] + bia1, 0.f);
            float v10 = fmaxf(acc[i][j][2] + bia0, 0.f);
            float v11 = fmaxf(acc[i][j][3] + bia1, 0.f);
            __nv_bfloat162 o0 = __floats2bfloat162_rn(v00, v01);
            __nv_bfloat162 o1 = __floats2bfloat162_rn(v10, v11);
            *(__nv_bfloat162*)&g_h[(size_t)r0 * 512 + c] = o0;
            *(__nv_bfloat162*)&g_h[(size_t)r1 * 512 + c] = o1;
        }
    }
}

// ---------------- GEMM2: expem = exp(h@W2 + b2) ----------------
__global__ __launch_bounds__(128) void gemm2_kernel(const float* __restrict__ W2,
                                                    const float* __restrict__ b2) {
    __shared__ __nv_bfloat16 As[128 * 72];  // [m][k] stride 72
    __shared__ __nv_bfloat16 Bs[40 * 72];   // [n][k] stride 72
    const int tid  = threadIdx.x;
    const int lane = tid & 31;
    const int wid  = tid >> 5;
    const int m0   = blockIdx.x * 128;
    const int wrow = wid * 32;
    const int gp   = lane >> 2;
    const int tg   = lane & 3;

    float acc[2][5][4];
#pragma unroll
    for (int i = 0; i < 2; i++)
#pragma unroll
        for (int j = 0; j < 5; j++)
#pragma unroll
            for (int k = 0; k < 4; k++) acc[i][j][k] = 0.f;

    for (int kt = 0; kt < 8; kt++) {
        __syncthreads();
        int k0 = kt * 64;
#pragma unroll
        for (int i = 0; i < 16; i++) {
            int idx = tid + i * 128;
            int r = idx >> 4, c = idx & 15;
            *(uint2*)&As[r * 72 + c * 4] =
                *(const uint2*)&g_h[(size_t)(m0 + r) * 512 + k0 + c * 4];
        }
        for (int idx = tid; idx < 40 * 64; idx += 128) {
            int k = idx & 63, n = idx >> 6;
            Bs[n * 72 + k] = (n < 37) ? __float2bfloat16(W2[(size_t)(k0 + k) * 37 + n])
                                      : __float2bfloat16(0.f);
        }
        __syncthreads();
#pragma unroll
        for (int kk = 0; kk < 64; kk += 16) {
            unsigned af[2][4], bfr[5][2];
#pragma unroll
            for (int i = 0; i < 2; i++) {
                int r = wrow + i * 16 + gp;
                af[i][0] = *(const unsigned*)&As[r * 72 + kk + tg * 2];
                af[i][1] = *(const unsigned*)&As[(r + 8) * 72 + kk + tg * 2];
                af[i][2] = *(const unsigned*)&As[r * 72 + kk + tg * 2 + 8];
                af[i][3] = *(const unsigned*)&As[(r + 8) * 72 + kk + tg * 2 + 8];
            }
#pragma unroll
            for (int j = 0; j < 5; j++) {
                int n = j * 8 + gp;
                bfr[j][0] = *(const unsigned*)&Bs[n * 72 + kk + tg * 2];
                bfr[j][1] = *(const unsigned*)&Bs[n * 72 + kk + tg * 2 + 8];
            }
#pragma unroll
            for (int i = 0; i < 2; i++)
#pragma unroll
                for (int j = 0; j < 5; j++) mma16816(acc[i][j], af[i], bfr[j]);
        }
    }

#pragma unroll
    for (int i = 0; i < 2; i++) {
        int r0 = m0 + wrow + i * 16 + gp;
        int r1 = r0 + 8;
#pragma unroll
        for (int j = 0; j < 5; j++) {
            int c = j * 8 + tg * 2;
            if (c < 37) {
                float bia = b2[c];
                g_expem[(size_t)r0 * 37 + c] = expf(acc[i][j][0] + bia);
                g_expem[(size_t)r1 * 37 + c] = expf(acc[i][j][2] + bia);
            }
            if (c + 1 < 37) {
                float bia = b2[c + 1];
                g_expem[(size_t)r0 * 37 + c + 1] = expf(acc[i][j][1] + bia);
                g_expem[(size_t)r1 * 37 + c + 1] = expf(acc[i][j][3] + bia);
            }
        }
    }
}

// ---------------- CRF: exp-domain forward + gold score ----------------
// One block per batch, 64 threads: warp0 = alpha recursion (shfl-based, no
// smem, no barrier), warp1 = gold path. em prefetched 2 steps ahead.
__global__ __launch_bounds__(64) void crf_kernel(const float* __restrict__ trans,
                                                 const float* __restrict__ startt,
                                                 const float* __restrict__ endt,
                                                 const int* __restrict__ labels) {
    __shared__ float sred[2];  // [0]=logZ, [1]=gold
    const int b = blockIdx.x, tid = threadIdx.x;
    const int len = g_len[b];
    const size_t base = (size_t)b * 512;
    const int* lab = labels + (size_t)b * 512;
    const unsigned FULL = 0xffffffffu;

    if (tid < 32) {
        const int t = tid;
        const int j1 = t + 32;
        const bool has2 = (t < 5);
        float E0[37], E1[37];
#pragma unroll 1
        for (int i = 0; i < 37; i++) {
            E0[i] = expf(trans[i * 37 + t]);
            E1[i] = has2 ? expf(trans[i * 37 + j1]) : 0.f;
        }
        const float ee0 = expf(endt[t]);
        const float ee1 = has2 ? expf(endt[j1]) : 0.f;

        float a0 = expf(startt[t]) * g_expem[base * 37 + t];
        float a1 = has2 ? expf(startt[j1]) * g_expem[base * 37 + j1] : 0.f;
        float logscale = 0.f;

        // em prefetch pipeline (depth 2)
        size_t r1r = base + 1, r2r = base + 2;
        float c0 = g_expem[r1r * 37 + t];
        float c1 = has2 ? g_expem[r1r * 37 + j1] : 0.f;
        float n0f = g_expem[r2r * 37 + t];
        float n1f = has2 ? g_expem[r2r * 37 + j1] : 0.f;

        for (int s = 1; s < len; s++) {
            // issue prefetch for s+2
            int sp = s + 2;
            size_t rowp = base + (sp < 512 ? sp : 511);
            float p0 = g_expem[rowp * 37 + t];
            float p1 = has2 ? g_expem[rowp * 37 + j1] : 0.f;

            // matvec: out = sum_i a[i] * E[i][.] , 4-way split chains
            float x0 = 0.f, x1 = 0.f, x2 = 0.f, x3 = 0.f;
            float y0 = 0.f, y1 = 0.f, y2 = 0.f, y3 = 0.f;
#pragma unroll
            for (int i = 0; i < 37; i++) {
                float v = (i < 32) ? __shfl_sync(FULL, a0, i)
                                   : __shfl_sync(FULL, a1, i - 32);
                switch (i & 3) {
                    case 0: x0 = fmaf(v, E0[i], x0); y0 = fmaf(v, E1[i], y0); break;
                    case 1: x1 = fmaf(v, E0[i], x1); y1 = fmaf(v, E1[i], y1); break;
                    case 2: x2 = fmaf(v, E0[i], x2); y2 = fmaf(v, E1[i], y2); break;
                    default: x3 = fmaf(v, E0[i], x3); y3 = fmaf(v, E1[i], y3); break;
                }
            }
            float na0 = ((x0 + x1) + (x2 + x3)) * c0;
            float na1 = ((y0 + y1) + (y2 + y3)) * c1;

            if ((s & 7) == 0) {  // cheap rescale: lane-0 magnitude proxy
                float scale = __shfl_sync(FULL, na0, 0);
                float inv = 1.f / scale;
                logscale += logf(scale);
                na0 *= inv;
                na1 *= inv;
            }
            a0 = na0;
            a1 = na1;
            c0 = n0f; c1 = n1f;
            n0f = p0; n1f = p1;
        }

        float z = a0 * ee0 + a1 * ee1;
#pragma unroll
        for (int off = 16; off; off >>= 1) z += __shfl_xor_sync(FULL, z, off);
        if (t == 0) sred[0] = logscale + logf(z);
    } else {
        const int k = tid - 32;
        float g = 0.f;
        for (int s = k; s < len; s += 32)
            g += logf(g_expem[(base + s) * 37 + lab[s]]);
        for (int s = 1 + k; s < len; s += 32)
            g += trans[lab[s - 1] * 37 + lab[s]];
        if (k == 0) g += startt[lab[0]] + endt[lab[len - 1]];
#pragma unroll
        for (int off = 16; off; off >>= 1) g += __shfl_xor_sync(FULL, g, off);
        if (k == 0) sred[1] = g;
    }
    __syncthreads();
    if (tid == 0) g_partial[b] = sred[0] - sred[1];
}

// ---------------- finalize: mean over batches ----------------
__global__ void finalize_kernel(float* __restrict__ out) {
    const int t = threadIdx.x;  // 32 threads
    float v = g_partial[t] + g_partial[t + 32];
#pragma unroll
    for (int off = 16; off; off >>= 1) v += __shfl_xor_sync(0xffffffffu, v, off);
    if (t == 0) out[0] = v * (1.f / 64.f);
}

// ---------------- launch ----------------
extern "C" void kernel_launch(void* const* d_in, const int* in_sizes, int n_in,
                              void* d_out, int out_size) {
    const float* X      = (const float*)d_in[0];
    const void*  mask   = d_in[1];
    const int*   labels = (const int*)d_in[2];
    const float* W1     = (const float*)d_in[3];
    const float* b1     = (const float*)d_in[4];
    const float* W2     = (const float*)d_in[5];
    const float* b2     = (const float*)d_in[6];
    const float* trans  = (const float*)d_in[7];
    const float* startt = (const float*)d_in[8];
    const float* endt   = (const float*)d_in[9];
    float* out = (float*)d_out;

    prep_kernel<<<64, 64>>>(mask);
    gemm1_kernel<<<dim3(4, 256), 256>>>(X, W1, b1);
    gemm2_kernel<<<256, 128>>>(W2, b2);
    crf_kernel<<<64, 64>>>(trans, startt, endt, labels);
    finalize_kernel<<<1, 32>>>(out);
}

// round 6
// speedup vs baseline: 1.6658x; 1.4921x over previous
#include <cuda_runtime.h>
#include <cuda_bf16.h>
#include <cstdint>
#include <cstddef>

// Shapes: B=64, S=512, D=768, H=512, T=37
// Inputs: 0 word_reprs f32[64,512,768], 1 word_mask (dtype sniffed) [64,512],
//         2 labels i32[64,512], 3 W1 f32[768,512], 4 b1 f32[512],
//         5 W2 f32[512,37], 6 b2 f32[37], 7 transitions f32[37,37],
//         8 start_trans f32[37], 9 end_trans f32[37]
// Output: scalar f32 loss.

// ---------------- device scratch (no runtime allocation) ----------------
__device__ __align__(16) __nv_bfloat16 g_h[(size_t)32768 * 512];   // 32 MB hidden
__device__ __align__(16) float g_expem[(size_t)32768 * 37];        // exp(logits)
__device__ int   g_len[64];
__device__ float g_partial[64];

typedef unsigned long long u64;

// ---------------- helpers ----------------
__device__ __forceinline__ void mma16816(float* d, const unsigned* a, const unsigned* b) {
    asm volatile(
        "mma.sync.aligned.m16n8k16.row.col.f32.bf16.bf16.f32 "
        "{%0,%1,%2,%3},{%4,%5,%6,%7},{%8,%9},{%0,%1,%2,%3};\n"
        : "+f"(d[0]), "+f"(d[1]), "+f"(d[2]), "+f"(d[3])
        : "r"(a[0]), "r"(a[1]), "r"(a[2]), "r"(a[3]), "r"(b[0]), "r"(b[1]));
}

__device__ __forceinline__ uint2 pack_bf16x4(float a, float b, float c, float d) {
    __nv_bfloat162 h0 = __floats2bfloat162_rn(a, b);
    __nv_bfloat162 h1 = __floats2bfloat162_rn(c, d);
    uint2 r;
    r.x = *reinterpret_cast<unsigned*>(&h0);
    r.y = *reinterpret_cast<unsigned*>(&h1);
    return r;
}

__device__ __forceinline__ u64 pack2(float lo, float hi) {
    u64 v;
    asm("mov.b64 %0, {%1, %2};" : "=l"(v) : "f"(lo), "f"(hi));
    return v;
}
__device__ __forceinline__ void unpack2(u64 v, float& lo, float& hi) {
    asm("mov.b64 {%0, %1}, %2;" : "=f"(lo), "=f"(hi) : "l"(v));
}
__device__ __forceinline__ u64 fma2(u64 a, u64 b, u64 c) {
    u64 d;
    asm("fma.rn.f32x2 %0, %1, %2, %3;" : "=l"(d) : "l"(a), "l"(b), "l"(c));
    return d;
}

// ---------------- lengths (mask dtype sniffed) ----------------
__global__ void prep_kernel(const void* __restrict__ mask) {
    __shared__ int rs[64];
    const int b = blockIdx.x, tid = threadIdx.x;
    const unsigned w0 = *(const unsigned*)mask;  // first 4 elems always true
    int cnt = 0;
    if (w0 == 0x01010101u) {                       // bool / uint8
        const unsigned char* p = (const unsigned char*)mask + (size_t)b * 512;
        for (int i = tid; i < 512; i += 64) cnt += (p[i] != 0);
    } else if (w0 == 0x3F800000u) {                // float32
        const float* p = (const float*)mask + (size_t)b * 512;
        for (int i = tid; i < 512; i += 64) cnt += (p[i] != 0.f);
    } else {                                       // int32
        const int* p = (const int*)mask + (size_t)b * 512;
        for (int i = tid; i < 512; i += 64) cnt += (p[i] != 0);
    }
    rs[tid] = cnt;
    __syncthreads();
    if (tid == 0) {
        int s = 0;
        for (int i = 0; i < 64; i++) s += rs[i];
        g_len[b] = s;
    }
}

// ---------------- GEMM1: h = relu(X@W1 + b1), bf16 mma ----------------
// BM=128 BN=128 BK=32, 256 threads (8 warps, 4x2), warp tile 32x64.
// B staged as [n][k] stride 44 (88 B rows, 8B aligned): each thread writes
// 4 consecutive k of one n via one STS.64 (was 16 scalar STS.16 @ 4-way).
#define BS_STRIDE 44
__global__ __launch_bounds__(256) void gemm1_kernel(const float* __restrict__ X,
                                                    const float* __restrict__ W1,
                                                    const float* __restrict__ b1) {
    __shared__ __nv_bfloat16 As[128 * 40];        // [m][k] stride 40
    __shared__ __nv_bfloat16 Bs[128 * BS_STRIDE]; // [n][k] stride 44
    const int tid  = threadIdx.x;
    const int lane = tid & 31;
    const int wid  = tid >> 5;
    const int wm   = wid & 3;            // 0..3 -> row
    const int wn   = wid >> 2;           // 0..1 -> col
    const int m0   = blockIdx.y * 128;
    const int n0   = blockIdx.x * 128;
    const int wrow = wm * 32;
    const int wcol = wn * 64;
    const int gp   = lane >> 2;          // 0..7
    const int tg   = lane & 3;           // 0..3

    float acc[2][8][4];
#pragma unroll
    for (int i = 0; i < 2; i++)
#pragma unroll
        for (int j = 0; j < 8; j++)
#pragma unroll
            for (int k = 0; k < 4; k++) acc[i][j][k] = 0.f;

    float4 ra[4];
    float  rb[4][4];
    const int nc = tid & 127;            // B-staging col (n) for this thread
    const int kgb = (tid >> 7) * 4;      // base k-group (0 or 4); +8 per i

    // prefetch k-tile 0
#pragma unroll
    for (int i = 0; i < 4; i++) {
        int idx = tid + i * 256;
        int r = idx >> 3, c = idx & 7;
        ra[i] = *(const float4*)(X + (size_t)(m0 + r) * 768 + c * 4);
    }
#pragma unroll
    for (int i = 0; i < 4; i++) {
        int kr = kgb + i * 8;            // 0..28
#pragma unroll
        for (int j = 0; j < 4; j++)
            rb[i][j] = W1[(size_t)(kr + j) * 512 + n0 + nc];
    }

    for (int kt = 0; kt < 24; kt++) {
        __syncthreads();
        // stage A (convert f32 -> bf16), one STS.64 per thread-iter
#pragma unroll
        for (int i = 0; i < 4; i++) {
            int idx = tid + i * 256;
            int r = idx >> 3, c = idx & 7;
            *(uint2*)&As[r * 40 + c * 4] = pack_bf16x4(ra[i].x, ra[i].y, ra[i].z, ra[i].w);
        }
        // stage B [n][k], one STS.64 per thread-iter
#pragma unroll
        for (int i = 0; i < 4; i++) {
            int kr = kgb + i * 8;
            *(uint2*)&Bs[nc * BS_STRIDE + kr] =
                pack_bf16x4(rb[i][0], rb[i][1], rb[i][2], rb[i][3]);
        }
        __syncthreads();
        if (kt < 23) {
            int k0 = (kt + 1) * 32;
#pragma unroll
            for (int i = 0; i < 4; i++) {
                int idx = tid + i * 256;
                int r = idx >> 3, c = idx & 7;
                ra[i] = *(const float4*)(X + (size_t)(m0 + r) * 768 + k0 + c * 4);
            }
#pragma unroll
            for (int i = 0; i < 4; i++) {
                int kr = kgb + i * 8;
#pragma unroll
                for (int j = 0; j < 4; j++)
                    rb[i][j] = W1[(size_t)(k0 + kr + j) * 512 + n0 + nc];
            }
        }
#pragma unroll
        for (int kk = 0; kk < 32; kk += 16) {
            unsigned af[2][4], bfr[8][2];
#pragma unroll
            for (int i = 0; i < 2; i++) {
                int r = wrow + i * 16 + gp;
                af[i][0] = *(const unsigned*)&As[r * 40 + kk + tg * 2];
                af[i][1] = *(const unsigned*)&As[(r + 8) * 40 + kk + tg * 2];
                af[i][2] = *(const unsigned*)&As[r * 40 + kk + tg * 2 + 8];
                af[i][3] = *(const unsigned*)&As[(r + 8) * 40 + kk + tg * 2 + 8];
            }
#pragma unroll
            for (int j = 0; j < 8; j++) {
                int n = wcol + j * 8 + gp;
                bfr[j][0] = *(const unsigned*)&Bs[n * BS_STRIDE + kk + tg * 2];
                bfr[j][1] = *(const unsigned*)&Bs[n * BS_STRIDE + kk + tg * 2 + 8];
            }
#pragma unroll
            for (int i = 0; i < 2; i++)
#pragma unroll
                for (int j = 0; j < 8; j++) mma16816(acc[i][j], af[i], bfr[j]);
        }
    }

    // epilogue: bias + relu, store bf16
#pragma unroll
    for (int i = 0; i < 2; i++) {
        int r0 = m0 + wrow + i * 16 + gp;
        int r1 = r0 + 8;
#pragma unroll
        for (int j = 0; j < 8; j++) {
            int c = n0 + wcol + j * 8 + tg * 2;
            float bia0 = b1[c], bia1 = b1[c + 1];
            float v00 = fmaxf(acc[i][j][0] + bia0, 0.f);
            float v01 = fmaxf(acc[i][j][1] + bia1, 0.f);
            float v10 = fmaxf(acc[i][j][2] + bia0, 0.f);
            float v11 = fmaxf(acc[i][j][3] + bia1, 0.f);
            __nv_bfloat162 o0 = __floats2bfloat162_rn(v00, v01);
            __nv_bfloat162 o1 = __floats2bfloat162_rn(v10, v11);
            *(__nv_bfloat162*)&g_h[(size_t)r0 * 512 + c] = o0;
            *(__nv_bfloat162*)&g_h[(size_t)r1 * 512 + c] = o1;
        }
    }
}

// ---------------- GEMM2: expem = exp(h@W2 + b2) ----------------
__global__ __launch_bounds__(128) void gemm2_kernel(const float* __restrict__ W2,
                                                    const float* __restrict__ b2) {
    __shared__ __nv_bfloat16 As[128 * 72];  // [m][k] stride 72
    __shared__ __nv_bfloat16 Bs[40 * 72];   // [n][k] stride 72
    const int tid  = threadIdx.x;
    const int lane = tid & 31;
    const int wid  = tid >> 5;
    const int m0   = blockIdx.x * 128;
    const int wrow = wid * 32;
    const int gp   = lane >> 2;
    const int tg   = lane & 3;

    float acc[2][5][4];
#pragma unroll
    for (int i = 0; i < 2; i++)
#pragma unroll
        for (int j = 0; j < 5; j++)
#pragma unroll
            for (int k = 0; k < 4; k++) acc[i][j][k] = 0.f;

    for (int kt = 0; kt < 8; kt++) {
        __syncthreads();
        int k0 = kt * 64;
#pragma unroll
        for (int i = 0; i < 16; i++) {
            int idx = tid + i * 128;
            int r = idx >> 4, c = idx & 15;
            *(uint2*)&As[r * 72 + c * 4] =
                *(const uint2*)&g_h[(size_t)(m0 + r) * 512 + k0 + c * 4];
        }
        for (int idx = tid; idx < 40 * 64; idx += 128) {
            int k = idx & 63, n = idx >> 6;
            Bs[n * 72 + k] = (n < 37) ? __float2bfloat16(W2[(size_t)(k0 + k) * 37 + n])
                                      : __float2bfloat16(0.f);
        }
        __syncthreads();
#pragma unroll
        for (int kk = 0; kk < 64; kk += 16) {
            unsigned af[2][4], bfr[5][2];
#pragma unroll
            for (int i = 0; i < 2; i++) {
                int r = wrow + i * 16 + gp;
                af[i][0] = *(const unsigned*)&As[r * 72 + kk + tg * 2];
                af[i][1] = *(const unsigned*)&As[(r + 8) * 72 + kk + tg * 2];
                af[i][2] = *(const unsigned*)&As[r * 72 + kk + tg * 2 + 8];
                af[i][3] = *(const unsigned*)&As[(r + 8) * 72 + kk + tg * 2 + 8];
            }
#pragma unroll
            for (int j = 0; j < 5; j++) {
                int n = j * 8 + gp;
                bfr[j][0] = *(const unsigned*)&Bs[n * 72 + kk + tg * 2];
                bfr[j][1] = *(const unsigned*)&Bs[n * 72 + kk + tg * 2 + 8];
            }
#pragma unroll
            for (int i = 0; i < 2; i++)
#pragma unroll
                for (int j = 0; j < 5; j++) mma16816(acc[i][j], af[i], bfr[j]);
        }
    }

#pragma unroll
    for (int i = 0; i < 2; i++) {
        int r0 = m0 + wrow + i * 16 + gp;
        int r1 = r0 + 8;
#pragma unroll
        for (int j = 0; j < 5; j++) {
            int c = j * 8 + tg * 2;
            if (c < 37) {
                float bia = b2[c];
                g_expem[(size_t)r0 * 37 + c] = expf(acc[i][j][0] + bia);
                g_expem[(size_t)r1 * 37 + c] = expf(acc[i][j][2] + bia);
            }
            if (c + 1 < 37) {
                float bia = b2[c + 1];
                g_expem[(size_t)r0 * 37 + c + 1] = expf(acc[i][j][1] + bia);
                g_expem[(size_t)r1 * 37 + c + 1] = expf(acc[i][j][3] + bia);
            }
        }
    }
}

// ---------------- CRF: exp-domain forward + gold score ----------------
// One block per batch. Warp0: alpha recursion with smem double buffer,
// LDS.64 pair loads + packed fma.rn.f32x2 (FFMA2), one __syncwarp per step.
// Warp1: gold path.
__global__ __launch_bounds__(64) void crf_kernel(const float* __restrict__ trans,
                                                 const float* __restrict__ startt,
                                                 const float* __restrict__ endt,
                                                 const int* __restrict__ labels) {
    __shared__ __align__(16) float sa[2][40];
    __shared__ float sred[2];  // [0]=logZ, [1]=gold
    const int b = blockIdx.x, tid = threadIdx.x;
    const int len = g_len[b];
    const size_t base = (size_t)b * 512;
    const int* lab = labels + (size_t)b * 512;
    const unsigned FULL = 0xffffffffu;

    if (tid < 32) {
        const int t = tid;
        const bool has2 = (t < 5);

        // E pairs: EP0[i] = (E[2i][t], E[2i+1][t]); EP1 for column t+32.
        u64 EP0[19], EP1[19];
#pragma unroll
        for (int i = 0; i < 19; i++) {
            const int i0 = 2 * i, i1 = 2 * i + 1;
            float e00 = expf(trans[i0 * 37 + t]);
            float e01 = (i1 < 37) ? expf(trans[i1 * 37 + t]) : 0.f;
            EP0[i] = pack2(e00, e01);
            float e10 = has2 ? expf(trans[i0 * 37 + t + 32]) : 0.f;
            float e11 = (has2 && i1 < 37) ? expf(trans[i1 * 37 + t + 32]) : 0.f;
            EP1[i] = pack2(e10, e11);
        }
        const float ee0 = expf(endt[t]);
        const float ee1 = has2 ? expf(endt[t + 32]) : 0.f;

        float a0 = expf(startt[t]) * g_expem[base * 37 + t];
        float a1 = has2 ? expf(startt[t + 32]) * g_expem[base * 37 + t + 32] : 0.f;
        sa[0][t] = a0;
        if (t < 8) {  // cols 32..36 + zero pads 37..39 on buffer 0
            sa[0][32 + t] = has2 ? a1 : 0.f;
            sa[1][32 + t] = 0.f;  // pads 37..39 of buffer 1 (cols 32..36 rewritten)
        }
        __syncwarp();

        // em prefetch pipeline (depth 2)
        float c0  = g_expem[(base + 1) * 37 + t];
        float c1  = has2 ? g_expem[(base + 1) * 37 + t + 32] : 0.f;
        float n0f = g_expem[(base + 2) * 37 + t];
        float n1f = has2 ? g_expem[(base + 2) * 37 + t + 32] : 0.f;
        float logscale = 0.f;

#pragma unroll 1
        for (int s = 1; s < len; s++) {
            int sp = s + 2;
            size_t rowp = base + (sp < 512 ? sp : 511);
            float p0 = g_expem[rowp * 37 + t];
            float p1 = has2 ? g_expem[rowp * 37 + t + 32] : 0.f;

            const float* buf = sa[(s - 1) & 1];
            u64 x2 = 0ull, y2 = 0ull;
#pragma unroll
            for (int i = 0; i < 19; i++) {
                u64 v = *(const u64*)&buf[2 * i];   // LDS.64 broadcast
                x2 = fma2(v, EP0[i], x2);
                y2 = fma2(v, EP1[i], y2);
            }
            float xl, xh, yl, yh;
            unpack2(x2, xl, xh);
            unpack2(y2, yl, yh);
            float na0 = (xl + xh) * c0;
            float na1 = (yl + yh) * c1;

            if ((s & 7) == 0) {  // periodic rescale (lane-0 magnitude proxy)
                float scale = __shfl_sync(FULL, na0, 0);
                logscale += logf(scale);
                float inv = 1.f / scale;
                na0 *= inv;
                na1 *= inv;
            }
            float* wb = sa[s & 1];
            wb[t] = na0;
            if (has2) wb[t + 32] = na1;
            __syncwarp();
            a0 = na0;
            a1 = na1;
            c0 = n0f; c1 = n1f;
            n0f = p0; n1f = p1;
        }

        float z = a0 * ee0 + a1 * ee1;
#pragma unroll
        for (int off = 16; off; off >>= 1) z += __shfl_xor_sync(FULL, z, off);
        if (t == 0) sred[0] = logscale + logf(z);
    } else {
        const int k = tid - 32;
        float g = 0.f;
        for (int s = k; s < len; s += 32)
            g += logf(g_expem[(base + s) * 37 + lab[s]]);
        for (int s = 1 + k; s < len; s += 32)
            g += trans[lab[s - 1] * 37 + lab[s]];
        if (k == 0) g += startt[lab[0]] + endt[lab[len - 1]];
#pragma unroll
        for (int off = 16; off; off >>= 1) g += __shfl_xor_sync(FULL, g, off);
        if (k == 0) sred[1] = g;
    }
    __syncthreads();
    if (tid == 0) g_partial[b] = sred[0] - sred[1];
}

// ---------------- finalize: mean over batches ----------------
__global__ void finalize_kernel(float* __restrict__ out) {
    const int t = threadIdx.x;  // 32 threads
    float v = g_partial[t] + g_partial[t + 32];
#pragma unroll
    for (int off = 16; off; off >>= 1) v += __shfl_xor_sync(0xffffffffu, v, off);
    if (t == 0) out[0] = v * (1.f / 64.f);
}

// ---------------- launch ----------------
extern "C" void kernel_launch(void* const* d_in, const int* in_sizes, int n_in,
                              void* d_out, int out_size) {
    const float* X      = (const float*)d_in[0];
    const void*  mask   = d_in[1];
    const int*   labels = (const int*)d_in[2];
    const float* W1     = (const float*)d_in[3];
    const float* b1     = (const float*)d_in[4];
    const float* W2     = (const float*)d_in[5];
    const float* b2     = (const float*)d_in[6];
    const float* trans  = (const float*)d_in[7];
    const float* startt = (const float*)d_in[8];
    const float* endt   = (const float*)d_in[9];
    float* out = (float*)d_out;

    prep_kernel<<<64, 64>>>(mask);
    gemm1_kernel<<<dim3(4, 256), 256>>>(X, W1, b1);
    gemm2_kernel<<<256, 128>>>(W2, b2);
    crf_kernel<<<64, 64>>>(trans, startt, endt, labels);
    finalize_kernel<<<1, 32>>>(out);
}

// round 7
// speedup vs baseline: 1.6970x; 1.0187x over previous
#include <cuda_runtime.h>
#include <cuda_bf16.h>
#include <cstdint>
#include <cstddef>

// Shapes: B=64, S=512, D=768, H=512, T=37
// Output: scalar f32 loss.

// ---------------- device scratch (no runtime allocation) ----------------
__device__ __align__(16) __nv_bfloat16 g_h[(size_t)32768 * 512];   // 32 MB hidden
__device__ __align__(16) float g_expem[(size_t)32768 * 37];        // exp(logits)
__device__ int   g_len[64];
__device__ float g_partial[64];

typedef unsigned long long u64;

// ---------------- helpers ----------------
__device__ __forceinline__ void mma16816(float* d, const unsigned* a, const unsigned* b) {
    asm volatile(
        "mma.sync.aligned.m16n8k16.row.col.f32.bf16.bf16.f32 "
        "{%0,%1,%2,%3},{%4,%5,%6,%7},{%8,%9},{%0,%1,%2,%3};\n"
        : "+f"(d[0]), "+f"(d[1]), "+f"(d[2]), "+f"(d[3])
        : "r"(a[0]), "r"(a[1]), "r"(a[2]), "r"(a[3]), "r"(b[0]), "r"(b[1]));
}

__device__ __forceinline__ uint2 pack_bf16x4(float a, float b, float c, float d) {
    __nv_bfloat162 h0 = __floats2bfloat162_rn(a, b);
    __nv_bfloat162 h1 = __floats2bfloat162_rn(c, d);
    uint2 r;
    r.x = *reinterpret_cast<unsigned*>(&h0);
    r.y = *reinterpret_cast<unsigned*>(&h1);
    return r;
}

__device__ __forceinline__ u64 pack2(float lo, float hi) {
    u64 v;
    asm("mov.b64 %0, {%1, %2};" : "=l"(v) : "f"(lo), "f"(hi));
    return v;
}
__device__ __forceinline__ void unpack2(u64 v, float& lo, float& hi) {
    asm("mov.b64 {%0, %1}, %2;" : "=f"(lo), "=f"(hi) : "l"(v));
}
__device__ __forceinline__ u64 fma2(u64 a, u64 b, u64 c) {
    u64 d;
    asm("fma.rn.f32x2 %0, %1, %2, %3;" : "=l"(d) : "l"(a), "l"(b), "l"(c));
    return d;
}
__device__ __forceinline__ u64 add2(u64 a, u64 b) {
    u64 d;
    asm("add.rn.f32x2 %0, %1, %2;" : "=l"(d) : "l"(a), "l"(b));
    return d;
}

// ---------------- lengths (mask dtype sniffed) ----------------
__global__ void prep_kernel(const void* __restrict__ mask) {
    __shared__ int rs[64];
    const int b = blockIdx.x, tid = threadIdx.x;
    const unsigned w0 = *(const unsigned*)mask;  // first 4 elems always true
    int cnt = 0;
    if (w0 == 0x01010101u) {                       // bool / uint8
        const unsigned char* p = (const unsigned char*)mask + (size_t)b * 512;
        for (int i = tid; i < 512; i += 64) cnt += (p[i] != 0);
    } else if (w0 == 0x3F800000u) {                // float32
        const float* p = (const float*)mask + (size_t)b * 512;
        for (int i = tid; i < 512; i += 64) cnt += (p[i] != 0.f);
    } else {                                       // int32
        const int* p = (const int*)mask + (size_t)b * 512;
        for (int i = tid; i < 512; i += 64) cnt += (p[i] != 0);
    }
    rs[tid] = cnt;
    __syncthreads();
    if (tid == 0) {
        int s = 0;
        for (int i = 0; i < 64; i++) s += rs[i];
        g_len[b] = s;
    }
}

// ---------------- GEMM1: h = relu(X@W1 + b1), bf16 mma ----------------
// grid 256 (one block per 128-row M tile). A slice 128x768 staged ONCE in
// smem bf16 (stride 776: MMA-read bank = 4*gp+tg, a perfect permutation).
// Inner loop over 4 N-tiles of 128; per (n,kt) stage B 32x128 only.
#define AS_STRIDE 776
#define BS_STRIDE 44
#define G1_SMEM ((128 * AS_STRIDE + 128 * BS_STRIDE) * 2)
__global__ __launch_bounds__(256) void gemm1_kernel(const float* __restrict__ X,
                                                    const float* __restrict__ W1,
                                                    const float* __restrict__ b1) {
    extern __shared__ __nv_bfloat16 smem[];
    __nv_bfloat16* As = smem;                       // [128][776]
    __nv_bfloat16* Bs = smem + 128 * AS_STRIDE;     // [128][44]
    const int tid  = threadIdx.x;
    const int lane = tid & 31;
    const int wid  = tid >> 5;
    const int wm   = wid & 3;            // 0..3 -> row
    const int wn   = wid >> 2;           // 0..1 -> col
    const int m0   = blockIdx.x * 128;
    const int wrow = wm * 32;
    const int gp   = lane >> 2;          // 0..7
    const int tg   = lane & 3;           // 0..3
    const int nc   = tid & 127;          // B-staging col (n)
    const int kgb  = (tid >> 7) * 4;     // base k-group

    // ---- stage A once: 128x768 f32 -> bf16, 96 float4 per thread ----
#pragma unroll 4
    for (int i = 0; i < 96; i++) {
        int idx = tid + i * 256;
        int r = idx / 192, c = idx % 192;
        float4 v = *(const float4*)(X + (size_t)(m0 + r) * 768 + c * 4);
        *(uint2*)&As[r * AS_STRIDE + c * 4] = pack_bf16x4(v.x, v.y, v.z, v.w);
    }
    __syncthreads();

    for (int nt = 0; nt < 4; nt++) {
        const int n0 = nt * 128;
        const int wcol = wn * 64;

        float acc[2][8][4];
#pragma unroll
        for (int i = 0; i < 2; i++)
#pragma unroll
            for (int j = 0; j < 8; j++)
#pragma unroll
                for (int k = 0; k < 4; k++) acc[i][j][k] = 0.f;

        float rb[4][4];
#pragma unroll
        for (int i = 0; i < 4; i++) {
            int kr = kgb + i * 8;
#pragma unroll
            for (int j = 0; j < 4; j++)
                rb[i][j] = W1[(size_t)(kr + j) * 512 + n0 + nc];
        }

        for (int kt = 0; kt < 24; kt++) {
            __syncthreads();  // Bs free (previous mma done)
#pragma unroll
            for (int i = 0; i < 4; i++) {
                int kr = kgb + i * 8;
                *(uint2*)&Bs[nc * BS_STRIDE + kr] =
                    pack_bf16x4(rb[i][0], rb[i][1], rb[i][2], rb[i][3]);
            }
            __syncthreads();
            if (kt < 23) {
                int k0 = (kt + 1) * 32;
#pragma unroll
                for (int i = 0; i < 4; i++) {
                    int kr = kgb + i * 8;
#pragma unroll
                    for (int j = 0; j < 4; j++)
                        rb[i][j] = W1[(size_t)(k0 + kr + j) * 512 + n0 + nc];
                }
            }
            const int kbase = kt * 32;
#pragma unroll
            for (int kk = 0; kk < 32; kk += 16) {
                unsigned af[2][4], bfr[8][2];
#pragma unroll
                for (int i = 0; i < 2; i++) {
                    int r = wrow + i * 16 + gp;
                    int ka = kbase + kk + tg * 2;
                    af[i][0] = *(const unsigned*)&As[r * AS_STRIDE + ka];
                    af[i][1] = *(const unsigned*)&As[(r + 8) * AS_STRIDE + ka];
                    af[i][2] = *(const unsigned*)&As[r * AS_STRIDE + ka + 8];
                    af[i][3] = *(const unsigned*)&As[(r + 8) * AS_STRIDE + ka + 8];
                }
#pragma unroll
                for (int j = 0; j < 8; j++) {
                    int n = wcol + j * 8 + gp;
                    bfr[j][0] = *(const unsigned*)&Bs[n * BS_STRIDE + kk + tg * 2];
                    bfr[j][1] = *(const unsigned*)&Bs[n * BS_STRIDE + kk + tg * 2 + 8];
                }
#pragma unroll
                for (int i = 0; i < 2; i++)
#pragma unroll
                    for (int j = 0; j < 8; j++) mma16816(acc[i][j], af[i], bfr[j]);
            }
        }

        // epilogue: bias + relu, store bf16
#pragma unroll
        for (int i = 0; i < 2; i++) {
            int r0 = m0 + wrow + i * 16 + gp;
            int r1 = r0 + 8;
#pragma unroll
            for (int j = 0; j < 8; j++) {
                int c = n0 + wcol + j * 8 + tg * 2;
                float bia0 = b1[c], bia1 = b1[c + 1];
                float v00 = fmaxf(acc[i][j][0] + bia0, 0.f);
                float v01 = fmaxf(acc[i][j][1] + bia1, 0.f);
                float v10 = fmaxf(acc[i][j][2] + bia0, 0.f);
                float v11 = fmaxf(acc[i][j][3] + bia1, 0.f);
                __nv_bfloat162 o0 = __floats2bfloat162_rn(v00, v01);
                __nv_bfloat162 o1 = __floats2bfloat162_rn(v10, v11);
                *(__nv_bfloat162*)&g_h[(size_t)r0 * 512 + c] = o0;
                *(__nv_bfloat162*)&g_h[(size_t)r1 * 512 + c] = o1;
            }
        }
        __syncthreads();  // before next n-tile reuses Bs
    }
}

// ---------------- GEMM2: expem = exp(h@W2 + b2) ----------------
__global__ __launch_bounds__(128) void gemm2_kernel(const float* __restrict__ W2,
                                                    const float* __restrict__ b2) {
    __shared__ __nv_bfloat16 As[128 * 72];  // [m][k] stride 72
    __shared__ __nv_bfloat16 Bs[40 * 72];   // [n][k] stride 72
    const int tid  = threadIdx.x;
    const int lane = tid & 31;
    const int wid  = tid >> 5;
    const int m0   = blockIdx.x * 128;
    const int wrow = wid * 32;
    const int gp   = lane >> 2;
    const int tg   = lane & 3;

    float acc[2][5][4];
#pragma unroll
    for (int i = 0; i < 2; i++)
#pragma unroll
        for (int j = 0; j < 5; j++)
#pragma unroll
            for (int k = 0; k < 4; k++) acc[i][j][k] = 0.f;

    for (int kt = 0; kt < 8; kt++) {
        __syncthreads();
        int k0 = kt * 64;
#pragma unroll
        for (int i = 0; i < 16; i++) {
            int idx = tid + i * 128;
            int r = idx >> 4, c = idx & 15;
            *(uint2*)&As[r * 72 + c * 4] =
                *(const uint2*)&g_h[(size_t)(m0 + r) * 512 + k0 + c * 4];
        }
        for (int idx = tid; idx < 40 * 64; idx += 128) {
            int k = idx & 63, n = idx >> 6;
            Bs[n * 72 + k] = (n < 37) ? __float2bfloat16(W2[(size_t)(k0 + k) * 37 + n])
                                      : __float2bfloat16(0.f);
        }
        __syncthreads();
#pragma unroll
        for (int kk = 0; kk < 64; kk += 16) {
            unsigned af[2][4], bfr[5][2];
#pragma unroll
            for (int i = 0; i < 2; i++) {
                int r = wrow + i * 16 + gp;
                af[i][0] = *(const unsigned*)&As[r * 72 + kk + tg * 2];
                af[i][1] = *(const unsigned*)&As[(r + 8) * 72 + kk + tg * 2];
                af[i][2] = *(const unsigned*)&As[r * 72 + kk + tg * 2 + 8];
                af[i][3] = *(const unsigned*)&As[(r + 8) * 72 + kk + tg * 2 + 8];
            }
#pragma unroll
            for (int j = 0; j < 5; j++) {
                int n = j * 8 + gp;
                bfr[j][0] = *(const unsigned*)&Bs[n * 72 + kk + tg * 2];
                bfr[j][1] = *(const unsigned*)&Bs[n * 72 + kk + tg * 2 + 8];
            }
#pragma unroll
            for (int i = 0; i < 2; i++)
#pragma unroll
                for (int j = 0; j < 5; j++) mma16816(acc[i][j], af[i], bfr[j]);
        }
    }

#pragma unroll
    for (int i = 0; i < 2; i++) {
        int r0 = m0 + wrow + i * 16 + gp;
        int r1 = r0 + 8;
#pragma unroll
        for (int j = 0; j < 5; j++) {
            int c = j * 8 + tg * 2;
            if (c < 37) {
                float bia = b2[c];
                g_expem[(size_t)r0 * 37 + c] = expf(acc[i][j][0] + bia);
                g_expem[(size_t)r1 * 37 + c] = expf(acc[i][j][2] + bia);
            }
            if (c + 1 < 37) {
                float bia = b2[c + 1];
                g_expem[(size_t)r0 * 37 + c + 1] = expf(acc[i][j][1] + bia);
                g_expem[(size_t)r1 * 37 + c + 1] = expf(acc[i][j][3] + bia);
            }
        }
    }
}

// ---------------- CRF: exp-domain forward + gold score ----------------
// One block per batch, 64 threads. Column c = tid (c<37 active). Each lane
// needs only EP[19] (38 regs -> no spill). 4 fma2 accumulator chains
// (depth 5). One __syncthreads per step. Rescale every 8 steps using the
// PREVIOUS alpha[0] from smem (uniform across warps, any positive scale is
// mathematically exact). Gold path computed by all 64 threads up front.
__global__ __launch_bounds__(64) void crf_kernel(const float* __restrict__ trans,
                                                 const float* __restrict__ startt,
                                                 const float* __restrict__ endt,
                                                 const int* __restrict__ labels) {
    __shared__ __align__(16) float sa[2][40];
    __shared__ float zbuf[40];
    __shared__ float gpart[2];
    __shared__ float sred[2];
    const int b = blockIdx.x, tid = threadIdx.x;
    const int len = g_len[b];
    const size_t base = (size_t)b * 512;
    const int* lab = labels + (size_t)b * 512;
    const unsigned FULL = 0xffffffffu;
    const bool act = tid < 37;
    const int c = act ? tid : 36;  // clamped for safe loads

    // ---- gold path: all 64 threads ----
    {
        float g = 0.f;
        for (int s = tid; s < len; s += 64)
            g += logf(g_expem[(base + s) * 37 + lab[s]]);
        for (int s = 1 + tid; s < len; s += 64)
            g += trans[lab[s - 1] * 37 + lab[s]];
        if (tid == 0) g += startt[lab[0]] + endt[lab[len - 1]];
#pragma unroll
        for (int off = 16; off; off >>= 1) g += __shfl_xor_sync(FULL, g, off);
        if ((tid & 31) == 0) gpart[tid >> 5] = g;
    }

    // ---- per-lane transition column, packed pairs ----
    u64 EP[19];
#pragma unroll 1
    for (int i = 0; i < 19; i++) {
        int i0 = 2 * i, i1 = 2 * i + 1;
        float e0 = act ? expf(trans[i0 * 37 + c]) : 0.f;
        float e1 = (act && i1 < 37) ? expf(trans[i1 * 37 + c]) : 0.f;
        EP[i] = pack2(e0, e1);
    }
    const float ee = act ? expf(endt[c]) : 0.f;

    // init alpha + pads
    if (act) sa[0][tid] = expf(startt[tid]) * g_expem[base * 37 + tid];
    if (tid >= 37 && tid < 40) {
        sa[0][tid] = 0.f;
        sa[1][tid] = 0.f;
        zbuf[tid] = 0.f;
    }
    float c0 = g_expem[(base + 1) * 37 + c];
    float n0 = g_expem[(base + 2) * 37 + c];
    float logscale = 0.f;
    float alast = 0.f;
    __syncthreads();

#pragma unroll 1
    for (int s = 1; s < len; s++) {
        int sp = s + 2;
        if (sp > 511) sp = 511;
        float p0 = g_expem[(base + sp) * 37 + c];

        const float* buf = sa[(s - 1) & 1];
        u64 A0 = 0ull, A1 = 0ull, A2 = 0ull, A3 = 0ull;
#pragma unroll
        for (int i = 0; i < 19; i++) {
            u64 v = *(const u64*)&buf[2 * i];  // LDS.64 broadcast
            switch (i & 3) {
                case 0:  A0 = fma2(v, EP[i], A0); break;
                case 1:  A1 = fma2(v, EP[i], A1); break;
                case 2:  A2 = fma2(v, EP[i], A2); break;
                default: A3 = fma2(v, EP[i], A3); break;
            }
        }
        u64 st = add2(add2(A0, A1), add2(A2, A3));
        float lo, hi;
        unpack2(st, lo, hi);
        float na = (lo + hi) * c0;

        if ((s & 7) == 0) {  // rescale via previous alpha[0] (uniform)
            float scale = buf[0];
            logscale += logf(scale);
            na *= (1.f / scale);
        }
        if (act) sa[s & 1][tid] = na;
        __syncthreads();
        alast = na;
        c0 = n0;
        n0 = p0;
    }

    if (act) zbuf[tid] = alast * ee;
    __syncthreads();
    if (tid < 32) {
        float z = zbuf[tid] + (tid < 8 ? zbuf[32 + tid] : 0.f);
#pragma unroll
        for (int off = 16; off; off >>= 1) z += __shfl_xor_sync(FULL, z, off);
        if (tid == 0) sred[0] = logscale + logf(z);
    }
    __syncthreads();
    if (tid == 0) g_partial[b] = sred[0] - (gpart[0] + gpart[1]);
}

// ---------------- finalize: mean over batches ----------------
__global__ void finalize_kernel(float* __restrict__ out) {
    const int t = threadIdx.x;  // 32 threads
    float v = g_partial[t] + g_partial[t + 32];
#pragma unroll
    for (int off = 16; off; off >>= 1) v += __shfl_xor_sync(0xffffffffu, v, off);
    if (t == 0) out[0] = v * (1.f / 64.f);
}

// ---------------- launch ----------------
extern "C" void kernel_launch(void* const* d_in, const int* in_sizes, int n_in,
                              void* d_out, int out_size) {
    const float* X      = (const float*)d_in[0];
    const void*  mask   = d_in[1];
    const int*   labels = (const int*)d_in[2];
    const float* W1     = (const float*)d_in[3];
    const float* b1     = (const float*)d_in[4];
    const float* W2     = (const float*)d_in[5];
    const float* b2     = (const float*)d_in[6];
    const float* trans  = (const float*)d_in[7];
    const float* startt = (const float*)d_in[8];
    const float* endt   = (const float*)d_in[9];
    float* out = (float*)d_out;

    static bool attr_done = false;
    if (!attr_done) {
        cudaFuncSetAttribute(gemm1_kernel,
                             cudaFuncAttributeMaxDynamicSharedMemorySize, G1_SMEM);
        attr_done = true;
    }

    prep_kernel<<<64, 64>>>(mask);
    gemm1_kernel<<<256, 256, G1_SMEM>>>(X, W1, b1);
    gemm2_kernel<<<256, 128>>>(W2, b2);
    crf_kernel<<<64, 64>>>(trans, startt, endt, labels);
    finalize_kernel<<<1, 32>>>(out);
}

// round 8
// speedup vs baseline: 1.9794x; 1.1664x over previous
#include <cuda_runtime.h>
#include <cuda_bf16.h>
#include <cstdint>
#include <cstddef>

// Shapes: B=64, S=512, D=768, H=512, T=37. Output: scalar f32 loss.

// ---------------- device scratch (no runtime allocation) ----------------
__device__ __align__(16) __nv_bfloat16 g_h[(size_t)32768 * 512];   // 32 MB hidden
__device__ __align__(16) float g_expem[(size_t)32768 * 37];        // exp(logits)
__device__ int   g_len[64];
__device__ float g_partial[64];

typedef unsigned long long u64;

// ---------------- helpers ----------------
__device__ __forceinline__ void mma16816(float* d, const unsigned* a, const unsigned* b) {
    asm volatile(
        "mma.sync.aligned.m16n8k16.row.col.f32.bf16.bf16.f32 "
        "{%0,%1,%2,%3},{%4,%5,%6,%7},{%8,%9},{%0,%1,%2,%3};\n"
        : "+f"(d[0]), "+f"(d[1]), "+f"(d[2]), "+f"(d[3])
        : "r"(a[0]), "r"(a[1]), "r"(a[2]), "r"(a[3]), "r"(b[0]), "r"(b[1]));
}

__device__ __forceinline__ uint2 pack_bf16x4(float a, float b, float c, float d) {
    __nv_bfloat162 h0 = __floats2bfloat162_rn(a, b);
    __nv_bfloat162 h1 = __floats2bfloat162_rn(c, d);
    uint2 r;
    r.x = *reinterpret_cast<unsigned*>(&h0);
    r.y = *reinterpret_cast<unsigned*>(&h1);
    return r;
}

__device__ __forceinline__ u64 pack2(float lo, float hi) {
    u64 v;
    asm("mov.b64 %0, {%1, %2};" : "=l"(v) : "f"(lo), "f"(hi));
    return v;
}
__device__ __forceinline__ void unpack2(u64 v, float& lo, float& hi) {
    asm("mov.b64 {%0, %1}, %2;" : "=f"(lo), "=f"(hi) : "l"(v));
}
__device__ __forceinline__ u64 fma2(u64 a, u64 b, u64 c) {
    u64 d;
    asm("fma.rn.f32x2 %0, %1, %2, %3;" : "=l"(d) : "l"(a), "l"(b), "l"(c));
    return d;
}
__device__ __forceinline__ u64 add2(u64 a, u64 b) {
    u64 d;
    asm("add.rn.f32x2 %0, %1, %2;" : "=l"(d) : "l"(a), "l"(b));
    return d;
}

// ---------------- lengths (mask dtype sniffed) ----------------
__global__ void prep_kernel(const void* __restrict__ mask) {
    __shared__ int rs[64];
    const int b = blockIdx.x, tid = threadIdx.x;
    const unsigned w0 = *(const unsigned*)mask;  // first 4 elems always true
    int cnt = 0;
    if (w0 == 0x01010101u) {
        const unsigned char* p = (const unsigned char*)mask + (size_t)b * 512;
        for (int i = tid; i < 512; i += 64) cnt += (p[i] != 0);
    } else if (w0 == 0x3F800000u) {
        const float* p = (const float*)mask + (size_t)b * 512;
        for (int i = tid; i < 512; i += 64) cnt += (p[i] != 0.f);
    } else {
        const int* p = (const int*)mask + (size_t)b * 512;
        for (int i = tid; i < 512; i += 64) cnt += (p[i] != 0);
    }
    rs[tid] = cnt;
    __syncthreads();
    if (tid == 0) {
        int s = 0;
        for (int i = 0; i < 64; i++) s += rs[i];
        g_len[b] = s;
    }
}

// ---------------- GEMM1: h = relu(X@W1 + b1), bf16 mma ----------------
// grid 256 (one block per 128-row M tile). A staged ONCE (stride 776,
// conflict-free mma reads). Bs DOUBLE-BUFFERED: one BAR per k-tile,
// W1 LDG for kt+2 hidden under the MMA phase of kt.
#define AS_STRIDE 776
#define BS_STRIDE 44
#define BS_TILE   (128 * BS_STRIDE)
#define G1_SMEM ((128 * AS_STRIDE + 2 * BS_TILE) * 2)
__global__ __launch_bounds__(256) void gemm1_kernel(const float* __restrict__ X,
                                                    const float* __restrict__ W1,
                                                    const float* __restrict__ b1) {
    extern __shared__ __nv_bfloat16 smem[];
    __nv_bfloat16* As  = smem;                    // [128][776]
    __nv_bfloat16* Bsb = smem + 128 * AS_STRIDE;  // 2 x [128][44]
    const int tid  = threadIdx.x;
    const int lane = tid & 31;
    const int wid  = tid >> 5;
    const int wm   = wid & 3;
    const int wn   = wid >> 2;
    const int m0   = blockIdx.x * 128;
    const int wrow = wm * 32;
    const int wcol = wn * 64;
    const int gp   = lane >> 2;
    const int tg   = lane & 3;
    const int nc   = tid & 127;          // B-staging col (n)
    const int kgb  = (tid >> 7) * 4;     // base k-group

    // ---- stage A once: 128x768 f32 -> bf16 ----
#pragma unroll 4
    for (int i = 0; i < 96; i++) {
        int idx = tid + i * 256;
        int r = idx / 192, c = idx % 192;
        float4 v = *(const float4*)(X + (size_t)(m0 + r) * 768 + c * 4);
        *(uint2*)&As[r * AS_STRIDE + c * 4] = pack_bf16x4(v.x, v.y, v.z, v.w);
    }
    __syncthreads();

    for (int nt = 0; nt < 4; nt++) {
        const int n0 = nt * 128;

        float acc[2][8][4];
#pragma unroll
        for (int i = 0; i < 2; i++)
#pragma unroll
            for (int j = 0; j < 8; j++)
#pragma unroll
                for (int k = 0; k < 4; k++) acc[i][j][k] = 0.f;

        float rb[4][4];
        // load + stage kt=0
#pragma unroll
        for (int i = 0; i < 4; i++) {
            int kr = kgb + i * 8;
#pragma unroll
            for (int j = 0; j < 4; j++)
                rb[i][j] = W1[(size_t)(kr + j) * 512 + n0 + nc];
        }
#pragma unroll
        for (int i = 0; i < 4; i++) {
            int kr = kgb + i * 8;
            *(uint2*)&Bsb[nc * BS_STRIDE + kr] =
                pack_bf16x4(rb[i][0], rb[i][1], rb[i][2], rb[i][3]);
        }
        // load kt=1
#pragma unroll
        for (int i = 0; i < 4; i++) {
            int kr = 32 + kgb + i * 8;
#pragma unroll
            for (int j = 0; j < 4; j++)
                rb[i][j] = W1[(size_t)(kr + j) * 512 + n0 + nc];
        }
        __syncthreads();

        for (int kt = 0; kt < 24; kt++) {
            // stage kt+1 into other buffer (rb holds kt+1)
            if (kt < 23) {
                __nv_bfloat16* Bw = Bsb + ((kt + 1) & 1) * BS_TILE;
#pragma unroll
                for (int i = 0; i < 4; i++) {
                    int kr = kgb + i * 8;
                    *(uint2*)&Bw[nc * BS_STRIDE + kr] =
                        pack_bf16x4(rb[i][0], rb[i][1], rb[i][2], rb[i][3]);
                }
            }
            // issue LDG for kt+2
            if (kt < 22) {
                int k0 = (kt + 2) * 32;
#pragma unroll
                for (int i = 0; i < 4; i++) {
                    int kr = k0 + kgb + i * 8;
#pragma unroll
                    for (int j = 0; j < 4; j++)
                        rb[i][j] = W1[(size_t)(kr + j) * 512 + n0 + nc];
                }
            }
            // MMA from buffer kt&1
            const __nv_bfloat16* Br = Bsb + (kt & 1) * BS_TILE;
            const int kbase = kt * 32;
#pragma unroll
            for (int kk = 0; kk < 32; kk += 16) {
                unsigned af[2][4], bfr[8][2];
#pragma unroll
                for (int i = 0; i < 2; i++) {
                    int r = wrow + i * 16 + gp;
                    int ka = kbase + kk + tg * 2;
                    af[i][0] = *(const unsigned*)&As[r * AS_STRIDE + ka];
                    af[i][1] = *(const unsigned*)&As[(r + 8) * AS_STRIDE + ka];
                    af[i][2] = *(const unsigned*)&As[r * AS_STRIDE + ka + 8];
                    af[i][3] = *(const unsigned*)&As[(r + 8) * AS_STRIDE + ka + 8];
                }
#pragma unroll
                for (int j = 0; j < 8; j++) {
                    int n = wcol + j * 8 + gp;
                    bfr[j][0] = *(const unsigned*)&Br[n * BS_STRIDE + kk + tg * 2];
                    bfr[j][1] = *(const unsigned*)&Br[n * BS_STRIDE + kk + tg * 2 + 8];
                }
#pragma unroll
                for (int i = 0; i < 2; i++)
#pragma unroll
                    for (int j = 0; j < 8; j++) mma16816(acc[i][j], af[i], bfr[j]);
            }
            __syncthreads();  // STS(kt+1) visible; reads of buf kt&1 done
        }

        // epilogue: bias + relu, store bf16
#pragma unroll
        for (int i = 0; i < 2; i++) {
            int r0 = m0 + wrow + i * 16 + gp;
            int r1 = r0 + 8;
#pragma unroll
            for (int j = 0; j < 8; j++) {
                int c = n0 + wcol + j * 8 + tg * 2;
                float bia0 = b1[c], bia1 = b1[c + 1];
                float v00 = fmaxf(acc[i][j][0] + bia0, 0.f);
                float v01 = fmaxf(acc[i][j][1] + bia1, 0.f);
                float v10 = fmaxf(acc[i][j][2] + bia0, 0.f);
                float v11 = fmaxf(acc[i][j][3] + bia1, 0.f);
                __nv_bfloat162 o0 = __floats2bfloat162_rn(v00, v01);
                __nv_bfloat162 o1 = __floats2bfloat162_rn(v10, v11);
                *(__nv_bfloat162*)&g_h[(size_t)r0 * 512 + c] = o0;
                *(__nv_bfloat162*)&g_h[(size_t)r1 * 512 + c] = o1;
            }
        }
        __syncthreads();
    }
}

// ---------------- GEMM2: expem = exp(h@W2 + b2) ----------------
__global__ __launch_bounds__(128) void gemm2_kernel(const float* __restrict__ W2,
                                                    const float* __restrict__ b2) {
    __shared__ __nv_bfloat16 As[128 * 72];
    __shared__ __nv_bfloat16 Bs[40 * 72];
    const int tid  = threadIdx.x;
    const int lane = tid & 31;
    const int wid  = tid >> 5;
    const int m0   = blockIdx.x * 128;
    const int wrow = wid * 32;
    const int gp   = lane >> 2;
    const int tg   = lane & 3;

    float acc[2][5][4];
#pragma unroll
    for (int i = 0; i < 2; i++)
#pragma unroll
        for (int j = 0; j < 5; j++)
#pragma unroll
            for (int k = 0; k < 4; k++) acc[i][j][k] = 0.f;

    for (int kt = 0; kt < 8; kt++) {
        __syncthreads();
        int k0 = kt * 64;
#pragma unroll
        for (int i = 0; i < 16; i++) {
            int idx = tid + i * 128;
            int r = idx >> 4, c = idx & 15;
            *(uint2*)&As[r * 72 + c * 4] =
                *(const uint2*)&g_h[(size_t)(m0 + r) * 512 + k0 + c * 4];
        }
        for (int idx = tid; idx < 40 * 64; idx += 128) {
            int k = idx & 63, n = idx >> 6;
            Bs[n * 72 + k] = (n < 37) ? __float2bfloat16(W2[(size_t)(k0 + k) * 37 + n])
                                      : __float2bfloat16(0.f);
        }
        __syncthreads();
#pragma unroll
        for (int kk = 0; kk < 64; kk += 16) {
            unsigned af[2][4], bfr[5][2];
#pragma unroll
            for (int i = 0; i < 2; i++) {
                int r = wrow + i * 16 + gp;
                af[i][0] = *(const unsigned*)&As[r * 72 + kk + tg * 2];
                af[i][1] = *(const unsigned*)&As[(r + 8) * 72 + kk + tg * 2];
                af[i][2] = *(const unsigned*)&As[r * 72 + kk + tg * 2 + 8];
                af[i][3] = *(const unsigned*)&As[(r + 8) * 72 + kk + tg * 2 + 8];
            }
#pragma unroll
            for (int j = 0; j < 5; j++) {
                int n = j * 8 + gp;
                bfr[j][0] = *(const unsigned*)&Bs[n * 72 + kk + tg * 2];
                bfr[j][1] = *(const unsigned*)&Bs[n * 72 + kk + tg * 2 + 8];
            }
#pragma unroll
            for (int i = 0; i < 2; i++)
#pragma unroll
                for (int j = 0; j < 5; j++) mma16816(acc[i][j], af[i], bfr[j]);
        }
    }

#pragma unroll
    for (int i = 0; i < 2; i++) {
        int r0 = m0 + wrow + i * 16 + gp;
        int r1 = r0 + 8;
#pragma unroll
        for (int j = 0; j < 5; j++) {
            int c = j * 8 + tg * 2;
            if (c < 37) {
                float bia = b2[c];
                g_expem[(size_t)r0 * 37 + c] = expf(acc[i][j][0] + bia);
                g_expem[(size_t)r1 * 37 + c] = expf(acc[i][j][2] + bia);
            }
            if (c + 1 < 37) {
                float bia = b2[c + 1];
                g_expem[(size_t)r0 * 37 + c + 1] = expf(acc[i][j][1] + bia);
                g_expem[(size_t)r1 * 37 + c + 1] = expf(acc[i][j][3] + bia);
            }
        }
    }
}

// ---------------- CRF: exp-domain forward + gold score ----------------
// One block per batch, 64 threads, lane = column (0..36 active; lanes >=37
// have all-zero EP so na==0 -> safe unguarded stores into 64-wide buffers).
// Main loop unrolled in groups of 8 (rescale compile-time at u==7): NO
// branches in the hot path. em prefetched one 8-step group ahead (MLP=8).
__device__ __forceinline__ float crf_step(const float* __restrict__ buf,
                                          const u64* __restrict__ EP, float em) {
    u64 A0 = 0ull, A1 = 0ull, A2 = 0ull, A3 = 0ull;
#pragma unroll
    for (int i = 0; i < 19; i++) {
        u64 v = *(const u64*)&buf[2 * i];  // LDS.64 broadcast
        switch (i & 3) {
            case 0:  A0 = fma2(v, EP[i], A0); break;
            case 1:  A1 = fma2(v, EP[i], A1); break;
            case 2:  A2 = fma2(v, EP[i], A2); break;
            default: A3 = fma2(v, EP[i], A3); break;
        }
    }
    u64 st = add2(add2(A0, A1), add2(A2, A3));
    float lo, hi;
    unpack2(st, lo, hi);
    return (lo + hi) * em;
}

__global__ __launch_bounds__(64) void crf_kernel(const float* __restrict__ trans,
                                                 const float* __restrict__ startt,
                                                 const float* __restrict__ endt,
                                                 const int* __restrict__ labels) {
    __shared__ __align__(16) float sa[2][64];
    __shared__ float gpart[2];
    __shared__ float zpart[2];
    const int b = blockIdx.x, tid = threadIdx.x;
    const int len = g_len[b];
    const size_t base = (size_t)b * 512;
    const int* lab = labels + base;
    const unsigned FULL = 0xffffffffu;
    const bool act = tid < 37;
    const int c = act ? tid : 36;

    // ---- gold path: all 64 threads ----
    {
        float g = 0.f;
        for (int s = tid; s < len; s += 64)
            g += logf(g_expem[(base + s) * 37 + lab[s]]);
        for (int s = 1 + tid; s < len; s += 64)
            g += trans[lab[s - 1] * 37 + lab[s]];
        if (tid == 0) g += startt[lab[0]] + endt[lab[len - 1]];
#pragma unroll
        for (int off = 16; off; off >>= 1) g += __shfl_xor_sync(FULL, g, off);
        if ((tid & 31) == 0) gpart[tid >> 5] = g;
    }

    // ---- per-lane transition column (zero for inactive lanes) ----
    u64 EP[19];
#pragma unroll 1
    for (int i = 0; i < 19; i++) {
        int i0 = 2 * i, i1 = 2 * i + 1;
        float e0 = act ? expf(trans[i0 * 37 + c]) : 0.f;
        float e1 = (act && i1 < 37) ? expf(trans[i1 * 37 + c]) : 0.f;
        EP[i] = pack2(e0, e1);
    }
    const float ee = act ? expf(endt[c]) : 0.f;
    const float* emp = g_expem + base * 37 + c;  // lane's em column

    sa[0][tid] = act ? expf(startt[tid]) * emp[0] : 0.f;
    sa[1][tid] = 0.f;
    __syncthreads();

    // em prefetch: cur = group g ems, nxt = group g+1 (len>=257 => safe)
    float cur[8], nxt[8];
#pragma unroll
    for (int u = 0; u < 8; u++) {
        cur[u] = emp[(1 + u) * 37];
        nxt[u] = emp[(9 + u) * 37];
    }

    const int G = (len - 1) >> 3;          // full 8-step groups (>=32)
    float logscale = 0.f;
    float na = 0.f;
    int s = 1;

#pragma unroll 1
    for (int g = 0; g < G; g++) {
        // groups start at odd s (1+8g): step u reads sa[u&1], writes sa[(u+1)&1]
#pragma unroll
        for (int u = 0; u < 8; u++) {
            const float* buf = sa[u & 1];
            na = crf_step(buf, EP, cur[u]);
            if (u == 7) {  // compile-time: rescale branch-free
                float scale = buf[0];
                logscale += logf(scale);
                na *= (1.f / scale);
            }
            sa[(u + 1) & 1][tid] = na;
            __syncthreads();
        }
        // rotate prefetch: cur <- nxt; nxt <- group g+2 ems
        int sbase = s + 16;
#pragma unroll
        for (int u = 0; u < 8; u++) {
            cur[u] = nxt[u];
            int ss = sbase + u;
            nxt[u] = emp[(ss < 512 ? ss : 511) * 37];
        }
        s += 8;
    }

    // tail: remaining (len-1) - 8G (<8) steps; ems are in cur[]
#pragma unroll 1
    for (int u = 0; s < len; s++, u++) {
        const float* buf = sa[(s - 1) & 1];
        na = crf_step(buf, EP, cur[u]);
        sa[s & 1][tid] = na;
        __syncthreads();
    }

    // logZ = logscale + log(sum na*ee)
    {
        float z = na * ee;
#pragma unroll
        for (int off = 16; off; off >>= 1) z += __shfl_xor_sync(FULL, z, off);
        if ((tid & 31) == 0) zpart[tid >> 5] = z;
    }
    __syncthreads();
    if (tid == 0)
        g_partial[b] = logscale + logf(zpart[0] + zpart[1]) - (gpart[0] + gpart[1]);
}

// ---------------- finalize: mean over batches ----------------
__global__ void finalize_kernel(float* __restrict__ out) {
    const int t = threadIdx.x;  // 32 threads
    float v = g_partial[t] + g_partial[t + 32];
#pragma unroll
    for (int off = 16; off; off >>= 1) v += __shfl_xor_sync(0xffffffffu, v, off);
    if (t == 0) out[0] = v * (1.f / 64.f);
}

// ---------------- launch ----------------
extern "C" void kernel_launch(void* const* d_in, const int* in_sizes, int n_in,
                              void* d_out, int out_size) {
    const float* X      = (const float*)d_in[0];
    const void*  mask   = d_in[1];
    const int*   labels = (const int*)d_in[2];
    const float* W1     = (const float*)d_in[3];
    const float* b1     = (const float*)d_in[4];
    const float* W2     = (const float*)d_in[5];
    const float* b2     = (const float*)d_in[6];
    const float* trans  = (const float*)d_in[7];
    const float* startt = (const float*)d_in[8];
    const float* endt   = (const float*)d_in[9];
    float* out = (float*)d_out;

    static bool attr_done = false;
    if (!attr_done) {
        cudaFuncSetAttribute(gemm1_kernel,
                             cudaFuncAttributeMaxDynamicSharedMemorySize, G1_SMEM);
        attr_done = true;
    }

    prep_kernel<<<64, 64>>>(mask);
    gemm1_kernel<<<256, 256, G1_SMEM>>>(X, W1, b1);
    gemm2_kernel<<<256, 128>>>(W2, b2);
    crf_kernel<<<64, 64>>>(trans, startt, endt, labels);
    finalize_kernel<<<1, 32>>>(out);
}

// round 10
// speedup vs baseline: 1.9959x; 1.0083x over previous
#include <cuda_runtime.h>
#include <cuda_bf16.h>
#include <cstdint>
#include <cstddef>

// Shapes: B=64, S=512, D=768, H=512, T=37. Output: scalar f32 loss.

// ---------------- device scratch (no runtime allocation) ----------------
__device__ __align__(16) __nv_bfloat16 g_h[(size_t)32768 * 512];   // 32 MB hidden
__device__ __align__(16) float g_expem[(size_t)32768 * 37];        // exp(logits)
__device__ float g_partial[64];

typedef unsigned long long u64;

// ---------------- helpers ----------------
__device__ __forceinline__ void mma16816(float* d, const unsigned* a, const unsigned* b) {
    asm volatile(
        "mma.sync.aligned.m16n8k16.row.col.f32.bf16.bf16.f32 "
        "{%0,%1,%2,%3},{%4,%5,%6,%7},{%8,%9},{%0,%1,%2,%3};\n"
        : "+f"(d[0]), "+f"(d[1]), "+f"(d[2]), "+f"(d[3])
        : "r"(a[0]), "r"(a[1]), "r"(a[2]), "r"(a[3]), "r"(b[0]), "r"(b[1]));
}

__device__ __forceinline__ uint2 pack_bf16x4(float a, float b, float c, float d) {
    __nv_bfloat162 h0 = __floats2bfloat162_rn(a, b);
    __nv_bfloat162 h1 = __floats2bfloat162_rn(c, d);
    uint2 r;
    r.x = *reinterpret_cast<unsigned*>(&h0);
    r.y = *reinterpret_cast<unsigned*>(&h1);
    return r;
}

__device__ __forceinline__ u64 pack2(float lo, float hi) {
    u64 v; asm("mov.b64 %0, {%1, %2};" : "=l"(v) : "f"(lo), "f"(hi)); return v;
}
__device__ __forceinline__ void unpack2(u64 v, float& lo, float& hi) {
    asm("mov.b64 {%0, %1}, %2;" : "=f"(lo), "=f"(hi) : "l"(v));
}
__device__ __forceinline__ u64 fma2(u64 a, u64 b, u64 c) {
    u64 d; asm("fma.rn.f32x2 %0, %1, %2, %3;" : "=l"(d) : "l"(a), "l"(b), "l"(c)); return d;
}
__device__ __forceinline__ u64 add2(u64 a, u64 b) {
    u64 d; asm("add.rn.f32x2 %0, %1, %2;" : "=l"(d) : "l"(a), "l"(b)); return d;
}

// ---------------- GEMM1: h = relu(X@W1 + b1), bf16 mma (R7, unchanged) ----------------
#define AS_STRIDE 776
#define BS_STRIDE 44
#define BS_TILE   (128 * BS_STRIDE)
#define G1_SMEM ((128 * AS_STRIDE + 2 * BS_TILE) * 2)
__global__ __launch_bounds__(256) void gemm1_kernel(const float* __restrict__ X,
                                                    const float* __restrict__ W1,
                                                    const float* __restrict__ b1) {
    extern __shared__ __nv_bfloat16 smem[];
    __nv_bfloat16* As  = smem;                    // [128][776]
    __nv_bfloat16* Bsb = smem + 128 * AS_STRIDE;  // 2 x [128][44]
    const int tid  = threadIdx.x;
    const int lane = tid & 31;
    const int wid  = tid >> 5;
    const int wm   = wid & 3;
    const int wn   = wid >> 2;
    const int m0   = blockIdx.x * 128;
    const int wrow = wm * 32;
    const int wcol = wn * 64;
    const int gp   = lane >> 2;
    const int tg   = lane & 3;
    const int nc   = tid & 127;
    const int kgb  = (tid >> 7) * 4;

#pragma unroll 4
    for (int i = 0; i < 96; i++) {
        int idx = tid + i * 256;
        int r = idx / 192, c = idx % 192;
        float4 v = *(const float4*)(X + (size_t)(m0 + r) * 768 + c * 4);
        *(uint2*)&As[r * AS_STRIDE + c * 4] = pack_bf16x4(v.x, v.y, v.z, v.w);
    }
    __syncthreads();

    for (int nt = 0; nt < 4; nt++) {
        const int n0 = nt * 128;

        float acc[2][8][4];
#pragma unroll
        for (int i = 0; i < 2; i++)
#pragma unroll
            for (int j = 0; j < 8; j++)
#pragma unroll
                for (int k = 0; k < 4; k++) acc[i][j][k] = 0.f;

        float rb[4][4];
#pragma unroll
        for (int i = 0; i < 4; i++) {
            int kr = kgb + i * 8;
#pragma unroll
            for (int j = 0; j < 4; j++)
                rb[i][j] = W1[(size_t)(kr + j) * 512 + n0 + nc];
        }
#pragma unroll
        for (int i = 0; i < 4; i++) {
            int kr = kgb + i * 8;
            *(uint2*)&Bsb[nc * BS_STRIDE + kr] =
                pack_bf16x4(rb[i][0], rb[i][1], rb[i][2], rb[i][3]);
        }
#pragma unroll
        for (int i = 0; i < 4; i++) {
            int kr = 32 + kgb + i * 8;
#pragma unroll
            for (int j = 0; j < 4; j++)
                rb[i][j] = W1[(size_t)(kr + j) * 512 + n0 + nc];
        }
        __syncthreads();

        for (int kt = 0; kt < 24; kt++) {
            if (kt < 23) {
                __nv_bfloat16* Bw = Bsb + ((kt + 1) & 1) * BS_TILE;
#pragma unroll
                for (int i = 0; i < 4; i++) {
                    int kr = kgb + i * 8;
                    *(uint2*)&Bw[nc * BS_STRIDE + kr] =
                        pack_bf16x4(rb[i][0], rb[i][1], rb[i][2], rb[i][3]);
                }
            }
            if (kt < 22) {
                int k0 = (kt + 2) * 32;
#pragma unroll
                for (int i = 0; i < 4; i++) {
                    int kr = k0 + kgb + i * 8;
#pragma unroll
                    for (int j = 0; j < 4; j++)
                        rb[i][j] = W1[(size_t)(kr + j) * 512 + n0 + nc];
                }
            }
            const __nv_bfloat16* Br = Bsb + (kt & 1) * BS_TILE;
            const int kbase = kt * 32;
#pragma unroll
            for (int kk = 0; kk < 32; kk += 16) {
                unsigned af[2][4], bfr[8][2];
#pragma unroll
                for (int i = 0; i < 2; i++) {
                    int r = wrow + i * 16 + gp;
                    int ka = kbase + kk + tg * 2;
                    af[i][0] = *(const unsigned*)&As[r * AS_STRIDE + ka];
                    af[i][1] = *(const unsigned*)&As[(r + 8) * AS_STRIDE + ka];
                    af[i][2] = *(const unsigned*)&As[r * AS_STRIDE + ka + 8];
                    af[i][3] = *(const unsigned*)&As[(r + 8) * AS_STRIDE + ka + 8];
                }
#pragma unroll
                for (int j = 0; j < 8; j++) {
                    int n = wcol + j * 8 + gp;
                    bfr[j][0] = *(const unsigned*)&Br[n * BS_STRIDE + kk + tg * 2];
                    bfr[j][1] = *(const unsigned*)&Br[n * BS_STRIDE + kk + tg * 2 + 8];
                }
#pragma unroll
                for (int i = 0; i < 2; i++)
#pragma unroll
                    for (int j = 0; j < 8; j++) mma16816(acc[i][j], af[i], bfr[j]);
            }
            __syncthreads();
        }

#pragma unroll
        for (int i = 0; i < 2; i++) {
            int r0 = m0 + wrow + i * 16 + gp;
            int r1 = r0 + 8;
#pragma unroll
            for (int j = 0; j < 8; j++) {
                int c = n0 + wcol + j * 8 + tg * 2;
                float bia0 = b1[c], bia1 = b1[c + 1];
                float v00 = fmaxf(acc[i][j][0] + bia0, 0.f);
                float v01 = fmaxf(acc[i][j][1] + bia1, 0.f);
                float v10 = fmaxf(acc[i][j][2] + bia0, 0.f);
                float v11 = fmaxf(acc[i][j][3] + bia1, 0.f);
                __nv_bfloat162 o0 = __floats2bfloat162_rn(v00, v01);
                __nv_bfloat162 o1 = __floats2bfloat162_rn(v10, v11);
                *(__nv_bfloat162*)&g_h[(size_t)r0 * 512 + c] = o0;
                *(__nv_bfloat162*)&g_h[(size_t)r1 * 512 + c] = o1;
            }
        }
        __syncthreads();
    }
}

// ---------------- GEMM2: expem = exp(h@W2 + b2) (unchanged) ----------------
__global__ __launch_bounds__(128) void gemm2_kernel(const float* __restrict__ W2,
                                                    const float* __restrict__ b2) {
    __shared__ __nv_bfloat16 As[128 * 72];
    __shared__ __nv_bfloat16 Bs[40 * 72];
    const int tid  = threadIdx.x;
    const int lane = tid & 31;
    const int wid  = tid >> 5;
    const int m0   = blockIdx.x * 128;
    const int wrow = wid * 32;
    const int gp   = lane >> 2;
    const int tg   = lane & 3;

    float acc[2][5][4];
#pragma unroll
    for (int i = 0; i < 2; i++)
#pragma unroll
        for (int j = 0; j < 5; j++)
#pragma unroll
            for (int k = 0; k < 4; k++) acc[i][j][k] = 0.f;

    for (int kt = 0; kt < 8; kt++) {
        __syncthreads();
        int k0 = kt * 64;
#pragma unroll
        for (int i = 0; i < 16; i++) {
            int idx = tid + i * 128;
            int r = idx >> 4, c = idx & 15;
            *(uint2*)&As[r * 72 + c * 4] =
                *(const uint2*)&g_h[(size_t)(m0 + r) * 512 + k0 + c * 4];
        }
        for (int idx = tid; idx < 40 * 64; idx += 128) {
            int k = idx & 63, n = idx >> 6;
            Bs[n * 72 + k] = (n < 37) ? __float2bfloat16(W2[(size_t)(k0 + k) * 37 + n])
                                      : __float2bfloat16(0.f);
        }
        __syncthreads();
#pragma unroll
        for (int kk = 0; kk < 64; kk += 16) {
            unsigned af[2][4], bfr[5][2];
#pragma unroll
            for (int i = 0; i < 2; i++) {
                int r = wrow + i * 16 + gp;
                af[i][0] = *(const unsigned*)&As[r * 72 + kk + tg * 2];
                af[i][1] = *(const unsigned*)&As[(r + 8) * 72 + kk + tg * 2];
                af[i][2] = *(const unsigned*)&As[r * 72 + kk + tg * 2 + 8];
                af[i][3] = *(const unsigned*)&As[(r + 8) * 72 + kk + tg * 2 + 8];
            }
#pragma unroll
            for (int j = 0; j < 5; j++) {
                int n = j * 8 + gp;
                bfr[j][0] = *(const unsigned*)&Bs[n * 72 + kk + tg * 2];
                bfr[j][1] = *(const unsigned*)&Bs[n * 72 + kk + tg * 2 + 8];
            }
#pragma unroll
            for (int i = 0; i < 2; i++)
#pragma unroll
                for (int j = 0; j < 5; j++) mma16816(acc[i][j], af[i], bfr[j]);
        }
    }

#pragma unroll
    for (int i = 0; i < 2; i++) {
        int r0 = m0 + wrow + i * 16 + gp;
        int r1 = r0 + 8;
#pragma unroll
        for (int j = 0; j < 5; j++) {
            int c = j * 8 + tg * 2;
            if (c < 37) {
                float bia = b2[c];
                g_expem[(size_t)r0 * 37 + c] = expf(acc[i][j][0] + bia);
                g_expem[(size_t)r1 * 37 + c] = expf(acc[i][j][2] + bia);
            }
            if (c + 1 < 37) {
                float bia = b2[c + 1];
                g_expem[(size_t)r0 * 37 + c + 1] = expf(acc[i][j][1] + bia);
                g_expem[(size_t)r1 * 37 + c + 1] = expf(acc[i][j][3] + bia);
            }
        }
    }
}

// ---------------- CRF: single-warp recursion, parallel gold path ----------------
// Warp0: alpha recursion alone (lane t owns cols t and t+32; cols >=37 are
// structurally zero via zero-packed EPH). __syncwarp per step — no cross-warp
// barrier in the hot loop. Warp1: gold path concurrently. One __syncthreads
// at the end. Length computed in-kernel per warp (prep kernel removed).
__global__ __launch_bounds__(64) void crf_kernel(const float* __restrict__ trans,
                                                 const float* __restrict__ startt,
                                                 const float* __restrict__ endt,
                                                 const int* __restrict__ labels,
                                                 const void* __restrict__ mask) {
    __shared__ __align__(16) float sa[2][64];
    __shared__ float gp_s;
    const int b = blockIdx.x, tid = threadIdx.x;
    const int lane = tid & 31;
    const unsigned FULL = 0xffffffffu;
    const size_t base = (size_t)b * 512;
    const int* lab = labels + base;

    // ---- per-warp length (mask dtype sniffed; first word always "true") ----
    int cnt = 0;
    const unsigned w0 = *(const unsigned*)mask;
    if (w0 == 0x01010101u) {                // bool / uint8
        const uint4* p = (const uint4*)((const unsigned char*)mask + base);
        uint4 v = p[lane];                  // 16 bytes per lane
        cnt = __popc(v.x & 0x01010101u) + __popc(v.y & 0x01010101u) +
              __popc(v.z & 0x01010101u) + __popc(v.w & 0x01010101u);
    } else if (w0 == 0x3F800000u) {         // float32
        const float* p = (const float*)mask + base;
        for (int i = lane; i < 512; i += 32) cnt += (p[i] != 0.f);
    } else {                                // int32
        const int* p = (const int*)mask + base;
        for (int i = lane; i < 512; i += 32) cnt += (p[i] != 0);
    }
#pragma unroll
    for (int off = 16; off; off >>= 1) cnt += __shfl_xor_sync(FULL, cnt, off);
    const int len = cnt;

    if (tid >= 32) {
        // ---- gold path (warp1, concurrent with recursion) ----
        float g = 0.f;
        for (int s = lane; s < len; s += 32)
            g += logf(g_expem[(base + s) * 37 + lab[s]]);
        for (int s = 1 + lane; s < len; s += 32)
            g += trans[lab[s - 1] * 37 + lab[s]];
        if (lane == 0) g += startt[lab[0]] + endt[lab[len - 1]];
#pragma unroll
        for (int off = 16; off; off >>= 1) g += __shfl_xor_sync(FULL, g, off);
        if (lane == 0) gp_s = g;
        __syncthreads();
        return;
    }

    // ---- recursion (warp0 only) ----
    const int t = tid;
    const bool hi = (t < 5);
    u64 EPL[19], EPH[19];
#pragma unroll 1
    for (int i = 0; i < 19; i++) {
        int i0 = 2 * i, i1 = 2 * i + 1;
        float eL0 = expf(trans[i0 * 37 + t]);
        float eL1 = (i1 < 37) ? expf(trans[i1 * 37 + t]) : 0.f;
        EPL[i] = pack2(eL0, eL1);
        float eH0 = hi ? expf(trans[i0 * 37 + t + 32]) : 0.f;
        float eH1 = (hi && i1 < 37) ? expf(trans[i1 * 37 + t + 32]) : 0.f;
        EPH[i] = pack2(eH0, eH1);
    }
    const float eeL = expf(endt[t]);
    const float eeH = hi ? expf(endt[t + 32]) : 0.f;
    const float* empL = g_expem + base * 37 + t;
    const float* empH = g_expem + base * 37 + (hi ? t + 32 : 36);

    sa[0][t] = expf(startt[t]) * empL[0];
    sa[0][t + 32] = (hi ? expf(startt[t + 32]) : 0.f) * empH[0];
    sa[1][t + 32] = 0.f;   // keep high pads of buffer 1 zero
    __syncwarp();

    // em prefetch, one 8-step group ahead (len >= 257 so s+16 always valid-ish)
    float curL[8], nxtL[8], curH[8], nxtH[8];
#pragma unroll
    for (int u = 0; u < 8; u++) {
        curL[u] = empL[(1 + u) * 37];
        nxtL[u] = empL[(9 + u) * 37];
        curH[u] = empH[(1 + u) * 37];
        nxtH[u] = empH[(9 + u) * 37];
    }

    const int G = (len - 1) >> 3;
    float logscale = 0.f;
    float naL = 0.f, naH = 0.f;
    int s = 1;

#pragma unroll 1
    for (int g = 0; g < G; g++) {
#pragma unroll
        for (int u = 0; u < 8; u++) {
            const float* buf = sa[u & 1];
            u64 L0 = 0ull, L1 = 0ull, H0 = 0ull, H1 = 0ull;
#pragma unroll
            for (int i = 0; i < 19; i++) {
                u64 v = *(const u64*)&buf[2 * i];  // LDS.64 broadcast
                if (i & 1) { L1 = fma2(v, EPL[i], L1); H1 = fma2(v, EPH[i], H1); }
                else       { L0 = fma2(v, EPL[i], L0); H0 = fma2(v, EPH[i], H0); }
            }
            float l0, l1, h0, h1;
            unpack2(add2(L0, L1), l0, l1);
            unpack2(add2(H0, H1), h0, h1);
            naL = (l0 + l1) * curL[u];
            naH = (h0 + h1) * curH[u];
            if (u == 7) {  // compile-time rescale, branch-free
                float scale = buf[0];
                logscale += logf(scale);
                float inv = 1.f / scale;
                naL *= inv;
                naH *= inv;
            }
            float* wb = sa[(u + 1) & 1];
            wb[t] = naL;
            wb[t + 32] = naH;   // zero for t>=5 (EPH zero) -> pads stay 0
            __syncwarp();
        }
        int sbase = s + 16;
#pragma unroll
        for (int u = 0; u < 8; u++) {
            curL[u] = nxtL[u];
            curH[u] = nxtH[u];
            int ss = sbase + u;
            ss = (ss < 512) ? ss : 511;
            nxtL[u] = empL[ss * 37];
            nxtH[u] = empH[ss * 37];
        }
        s += 8;
    }

    // tail (<8 steps), ems already in curL/curH
#pragma unroll 1
    for (int u = 0; s < len; s++, u++) {
        const float* buf = sa[(s - 1) & 1];
        u64 L0 = 0ull, L1 = 0ull, H0 = 0ull, H1 = 0ull;
#pragma unroll
        for (int i = 0; i < 19; i++) {
            u64 v = *(const u64*)&buf[2 * i];
            if (i & 1) { L1 = fma2(v, EPL[i], L1); H1 = fma2(v, EPH[i], H1); }
            else       { L0 = fma2(v, EPL[i], L0); H0 = fma2(v, EPH[i], H0); }
        }
        float l0, l1, h0, h1;
        unpack2(add2(L0, L1), l0, l1);
        unpack2(add2(H0, H1), h0, h1);
        naL = (l0 + l1) * curL[u];
        naH = (h0 + h1) * curH[u];
        float* wb = sa[s & 1];
        wb[t] = naL;
        wb[t + 32] = naH;
        __syncwarp();
    }

    float z = naL * eeL + naH * eeH;
#pragma unroll
    for (int off = 16; off; off >>= 1) z += __shfl_xor_sync(FULL, z, off);
    __syncthreads();  // pairs with warp1's
    if (tid == 0) g_partial[b] = logscale + logf(z) - gp_s;
}

// ---------------- finalize: mean over batches ----------------
__global__ void finalize_kernel(float* __restrict__ out) {
    const int t = threadIdx.x;
    float v = g_partial[t] + g_partial[t + 32];
#pragma unroll
    for (int off = 16; off; off >>= 1) v += __shfl_xor_sync(0xffffffffu, v, off);
    if (t == 0) out[0] = v * (1.f / 64.f);
}

// ---------------- launch ----------------
extern "C" void kernel_launch(void* const* d_in, const int* in_sizes, int n_in,
                              void* d_out, int out_size) {
    const float* X      = (const float*)d_in[0];
    const void*  mask   = d_in[1];
    const int*   labels = (const int*)d_in[2];
    const float* W1     = (const float*)d_in[3];
    const float* b1     = (const float*)d_in[4];
    const float* W2     = (const float*)d_in[5];
    const float* b2     = (const float*)d_in[6];
    const float* trans  = (const float*)d_in[7];
    const float* startt = (const float*)d_in[8];
    const float* endt   = (const float*)d_in[9];
    float* out = (float*)d_out;

    static bool attr_done = false;
    if (!attr_done) {
        cudaFuncSetAttribute(gemm1_kernel,
                             cudaFuncAttributeMaxDynamicSharedMemorySize, G1_SMEM);
        attr_done = true;
    }

    gemm1_kernel<<<256, 256, G1_SMEM>>>(X, W1, b1);
    gemm2_kernel<<<256, 128>>>(W2, b2);
    crf_kernel<<<64, 64>>>(trans, startt, endt, labels, mask);
    finalize_kernel<<<1, 32>>>(out);
}

// round 11
// speedup vs baseline: 2.3901x; 1.1975x over previous
#include <cuda_runtime.h>
#include <cuda_bf16.h>
#include <cstdint>
#include <cstddef>

// Shapes: B=64, S=512, D=768, H=512, T=37. Output: scalar f32 loss.

// ---------------- device scratch (no runtime allocation) ----------------
__device__ __align__(16) __nv_bfloat16 g_h[(size_t)32768 * 512];   // 32 MB hidden
__device__ __align__(16) float g_expem[(size_t)32768 * 37];        // exp(logits)
__device__ float g_partial[64];

typedef unsigned long long u64;

// ---------------- helpers ----------------
__device__ __forceinline__ void mma16816(float* d, const unsigned* a, const unsigned* b) {
    asm volatile(
        "mma.sync.aligned.m16n8k16.row.col.f32.bf16.bf16.f32 "
        "{%0,%1,%2,%3},{%4,%5,%6,%7},{%8,%9},{%0,%1,%2,%3};\n"
        : "+f"(d[0]), "+f"(d[1]), "+f"(d[2]), "+f"(d[3])
        : "r"(a[0]), "r"(a[1]), "r"(a[2]), "r"(a[3]), "r"(b[0]), "r"(b[1]));
}

__device__ __forceinline__ void ldsm_x4(unsigned& r0, unsigned& r1, unsigned& r2,
                                        unsigned& r3, uint32_t addr) {
    asm volatile("ldmatrix.sync.aligned.m8n8.x4.shared.b16 {%0,%1,%2,%3}, [%4];"
                 : "=r"(r0), "=r"(r1), "=r"(r2), "=r"(r3) : "r"(addr));
}

__device__ __forceinline__ uint32_t smem_u32(const void* p) {
    uint32_t a;
    asm("{ .reg .u64 t; cvta.to.shared.u64 t, %1; cvt.u32.u64 %0, t; }" : "=r"(a) : "l"(p));
    return a;
}

__device__ __forceinline__ uint2 pack_bf16x4(float a, float b, float c, float d) {
    __nv_bfloat162 h0 = __floats2bfloat162_rn(a, b);
    __nv_bfloat162 h1 = __floats2bfloat162_rn(c, d);
    uint2 r;
    r.x = *reinterpret_cast<unsigned*>(&h0);
    r.y = *reinterpret_cast<unsigned*>(&h1);
    return r;
}

__device__ __forceinline__ u64 pack2(float lo, float hi) {
    u64 v; asm("mov.b64 %0, {%1, %2};" : "=l"(v) : "f"(lo), "f"(hi)); return v;
}
__device__ __forceinline__ void unpack2(u64 v, float& lo, float& hi) {
    asm("mov.b64 {%0, %1}, %2;" : "=f"(lo), "=f"(hi) : "l"(v));
}
__device__ __forceinline__ u64 fma2(u64 a, u64 b, u64 c) {
    u64 d; asm("fma.rn.f32x2 %0, %1, %2, %3;" : "=l"(d) : "l"(a), "l"(b), "l"(c)); return d;
}
__device__ __forceinline__ u64 add2(u64 a, u64 b) {
    u64 d; asm("add.rn.f32x2 %0, %1, %2;" : "=l"(d) : "l"(a), "l"(b)); return d;
}

// ---------------- GEMM1: h = relu(X@W1 + b1), bf16 mma + LDSM ----------------
#define AS_STRIDE 776
#define BS_STRIDE 40
#define BS_TILE   (128 * BS_STRIDE)
#define G1_SMEM ((128 * AS_STRIDE + 2 * BS_TILE) * 2)
__global__ __launch_bounds__(256) void gemm1_kernel(const float* __restrict__ X,
                                                    const float* __restrict__ W1,
                                                    const float* __restrict__ b1) {
    extern __shared__ __nv_bfloat16 smem[];
    __nv_bfloat16* As  = smem;                    // [128][776]
    __nv_bfloat16* Bsb = smem + 128 * AS_STRIDE;  // 2 x [128][40]
    const int tid  = threadIdx.x;
    const int lane = tid & 31;
    const int wid  = tid >> 5;
    const int wm   = wid & 3;
    const int wn   = wid >> 2;
    const int m0   = blockIdx.x * 128;
    const int wrow = wm * 32;
    const int wcol = wn * 64;
    const int gp   = lane >> 2;
    const int tg   = lane & 3;
    const int nc   = tid & 127;
    const int kgb  = (tid >> 7) * 4;

    // LDSM lane address components
    const uint32_t as_u32 = smem_u32(As);
    const uint32_t bs_u32 = as_u32 + 128 * AS_STRIDE * 2;
    const int rowA  = wrow + (lane & 7) + ((lane >> 3) & 1) * 8;
    const int kaddA = ((lane >> 4) & 1) * 8;
    const uint32_t aoff = as_u32 + (uint32_t)(rowA * AS_STRIDE + kaddA) * 2;
    const int rowB  = wcol + (lane & 7) + ((lane >> 4) & 1) * 8;
    const int kaddB = ((lane >> 3) & 1) * 8;
    const uint32_t boff = (uint32_t)(rowB * BS_STRIDE + kaddB) * 2;

#pragma unroll 4
    for (int i = 0; i < 96; i++) {
        int idx = tid + i * 256;
        int r = idx / 192, c = idx % 192;
        float4 v = *(const float4*)(X + (size_t)(m0 + r) * 768 + c * 4);
        *(uint2*)&As[r * AS_STRIDE + c * 4] = pack_bf16x4(v.x, v.y, v.z, v.w);
    }
    __syncthreads();

    for (int nt = 0; nt < 4; nt++) {
        const int n0 = nt * 128;

        float acc[2][8][4];
#pragma unroll
        for (int i = 0; i < 2; i++)
#pragma unroll
            for (int j = 0; j < 8; j++)
#pragma unroll
                for (int k = 0; k < 4; k++) acc[i][j][k] = 0.f;

        float rb[4][4];
#pragma unroll
        for (int i = 0; i < 4; i++) {
            int kr = kgb + i * 8;
#pragma unroll
            for (int j = 0; j < 4; j++)
                rb[i][j] = W1[(size_t)(kr + j) * 512 + n0 + nc];
        }
#pragma unroll
        for (int i = 0; i < 4; i++) {
            int kr = kgb + i * 8;
            *(uint2*)&Bsb[nc * BS_STRIDE + kr] =
                pack_bf16x4(rb[i][0], rb[i][1], rb[i][2], rb[i][3]);
        }
#pragma unroll
        for (int i = 0; i < 4; i++) {
            int kr = 32 + kgb + i * 8;
#pragma unroll
            for (int j = 0; j < 4; j++)
                rb[i][j] = W1[(size_t)(kr + j) * 512 + n0 + nc];
        }
        __syncthreads();

        for (int kt = 0; kt < 24; kt++) {
            if (kt < 23) {
                __nv_bfloat16* Bw = Bsb + ((kt + 1) & 1) * BS_TILE;
#pragma unroll
                for (int i = 0; i < 4; i++) {
                    int kr = kgb + i * 8;
                    *(uint2*)&Bw[nc * BS_STRIDE + kr] =
                        pack_bf16x4(rb[i][0], rb[i][1], rb[i][2], rb[i][3]);
                }
            }
            if (kt < 22) {
                int k0 = (kt + 2) * 32;
#pragma unroll
                for (int i = 0; i < 4; i++) {
                    int kr = k0 + kgb + i * 8;
#pragma unroll
                    for (int j = 0; j < 4; j++)
                        rb[i][j] = W1[(size_t)(kr + j) * 512 + n0 + nc];
                }
            }
            const uint32_t bbase = bs_u32 + (uint32_t)((kt & 1) * BS_TILE * 2) + boff;
            const int kbase = kt * 32;
#pragma unroll
            for (int kk = 0; kk < 32; kk += 16) {
                const uint32_t ka2 = (uint32_t)(kbase + kk) * 2;
                unsigned af[2][4], bfr[8][2];
                ldsm_x4(af[0][0], af[0][1], af[0][2], af[0][3], aoff + ka2);
                ldsm_x4(af[1][0], af[1][1], af[1][2], af[1][3],
                        aoff + 16 * AS_STRIDE * 2 + ka2);
                const uint32_t bb = bbase + (uint32_t)kk * 2;
#pragma unroll
                for (int j2 = 0; j2 < 4; j2++)
                    ldsm_x4(bfr[2 * j2][0], bfr[2 * j2][1],
                            bfr[2 * j2 + 1][0], bfr[2 * j2 + 1][1],
                            bb + (uint32_t)(j2 * 16 * BS_STRIDE) * 2);
#pragma unroll
                for (int i = 0; i < 2; i++)
#pragma unroll
                    for (int j = 0; j < 8; j++) mma16816(acc[i][j], af[i], bfr[j]);
            }
            __syncthreads();
        }

#pragma unroll
        for (int i = 0; i < 2; i++) {
            int r0 = m0 + wrow + i * 16 + gp;
            int r1 = r0 + 8;
#pragma unroll
            for (int j = 0; j < 8; j++) {
                int c = n0 + wcol + j * 8 + tg * 2;
                float bia0 = b1[c], bia1 = b1[c + 1];
                float v00 = fmaxf(acc[i][j][0] + bia0, 0.f);
                float v01 = fmaxf(acc[i][j][1] + bia1, 0.f);
                float v10 = fmaxf(acc[i][j][2] + bia0, 0.f);
                float v11 = fmaxf(acc[i][j][3] + bia1, 0.f);
                __nv_bfloat162 o0 = __floats2bfloat162_rn(v00, v01);
                __nv_bfloat162 o1 = __floats2bfloat162_rn(v10, v11);
                *(__nv_bfloat162*)&g_h[(size_t)r0 * 512 + c] = o0;
                *(__nv_bfloat162*)&g_h[(size_t)r1 * 512 + c] = o1;
            }
        }
        __syncthreads();
    }
}

// ---------------- GEMM2: expem = exp(h@W2 + b2) (unchanged) ----------------
__global__ __launch_bounds__(128) void gemm2_kernel(const float* __restrict__ W2,
                                                    const float* __restrict__ b2) {
    __shared__ __nv_bfloat16 As[128 * 72];
    __shared__ __nv_bfloat16 Bs[40 * 72];
    const int tid  = threadIdx.x;
    const int lane = tid & 31;
    const int wid  = tid >> 5;
    const int m0   = blockIdx.x * 128;
    const int wrow = wid * 32;
    const int gp   = lane >> 2;
    const int tg   = lane & 3;

    float acc[2][5][4];
#pragma unroll
    for (int i = 0; i < 2; i++)
#pragma unroll
        for (int j = 0; j < 5; j++)
#pragma unroll
            for (int k = 0; k < 4; k++) acc[i][j][k] = 0.f;

    for (int kt = 0; kt < 8; kt++) {
        __syncthreads();
        int k0 = kt * 64;
#pragma unroll
        for (int i = 0; i < 16; i++) {
            int idx = tid + i * 128;
            int r = idx >> 4, c = idx & 15;
            *(uint2*)&As[r * 72 + c * 4] =
                *(const uint2*)&g_h[(size_t)(m0 + r) * 512 + k0 + c * 4];
        }
        for (int idx = tid; idx < 40 * 64; idx += 128) {
            int k = idx & 63, n = idx >> 6;
            Bs[n * 72 + k] = (n < 37) ? __float2bfloat16(W2[(size_t)(k0 + k) * 37 + n])
                                      : __float2bfloat16(0.f);
        }
        __syncthreads();
#pragma unroll
        for (int kk = 0; kk < 64; kk += 16) {
            unsigned af[2][4], bfr[5][2];
#pragma unroll
            for (int i = 0; i < 2; i++) {
                int r = wrow + i * 16 + gp;
                af[i][0] = *(const unsigned*)&As[r * 72 + kk + tg * 2];
                af[i][1] = *(const unsigned*)&As[(r + 8) * 72 + kk + tg * 2];
                af[i][2] = *(const unsigned*)&As[r * 72 + kk + tg * 2 + 8];
                af[i][3] = *(const unsigned*)&As[(r + 8) * 72 + kk + tg * 2 + 8];
            }
#pragma unroll
            for (int j = 0; j < 5; j++) {
                int n = j * 8 + gp;
                bfr[j][0] = *(const unsigned*)&Bs[n * 72 + kk + tg * 2];
                bfr[j][1] = *(const unsigned*)&Bs[n * 72 + kk + tg * 2 + 8];
            }
#pragma unroll
            for (int i = 0; i < 2; i++)
#pragma unroll
                for (int j = 0; j < 5; j++) mma16816(acc[i][j], af[i], bfr[j]);
        }
    }

#pragma unroll
    for (int i = 0; i < 2; i++) {
        int r0 = m0 + wrow + i * 16 + gp;
        int r1 = r0 + 8;
#pragma unroll
        for (int j = 0; j < 5; j++) {
            int c = j * 8 + tg * 2;
            if (c < 37) {
                float bia = b2[c];
                g_expem[(size_t)r0 * 37 + c] = expf(acc[i][j][0] + bia);
                g_expem[(size_t)r1 * 37 + c] = expf(acc[i][j][2] + bia);
            }
            if (c + 1 < 37) {
                float bia = b2[c + 1];
                g_expem[(size_t)r0 * 37 + c + 1] = expf(acc[i][j][1] + bia);
                g_expem[(size_t)r1 * 37 + c + 1] = expf(acc[i][j][3] + bia);
            }
        }
    }
}

// ---------------- CRF: forward/backward split ----------------
// Z = sum_i alpha_s[i]*beta_s[i] for any s. Warp0: alpha forward to mid.
// Warp1: g = em*beta backward from len-1 down to mid (uses E rows).
// Warp2: gold path. Combine: Z = sum alpha_mid * g_mid / em_mid.
__global__ __launch_bounds__(96) void crf_kernel(const float* __restrict__ trans,
                                                 const float* __restrict__ startt,
                                                 const float* __restrict__ endt,
                                                 const int* __restrict__ labels,
                                                 const void* __restrict__ mask) {
    __shared__ __align__(16) float sa[2][64];  // forward alpha
    __shared__ __align__(16) float sb[2][64];  // backward g
    __shared__ float gp_s, lsB_s;
    const int b = blockIdx.x, tid = threadIdx.x;
    const int lane = tid & 31;
    const int wid  = tid >> 5;
    const unsigned FULL = 0xffffffffu;
    const size_t base = (size_t)b * 512;
    const int* lab = labels + base;

    // ---- per-warp length (mask dtype sniffed) ----
    int cnt = 0;
    const unsigned w0 = *(const unsigned*)mask;
    if (w0 == 0x01010101u) {
        const uint4* p = (const uint4*)((const unsigned char*)mask + base);
        uint4 v = p[lane];
        cnt = __popc(v.x & 0x01010101u) + __popc(v.y & 0x01010101u) +
              __popc(v.z & 0x01010101u) + __popc(v.w & 0x01010101u);
    } else if (w0 == 0x3F800000u) {
        const float* p = (const float*)mask + base;
        for (int i = lane; i < 512; i += 32) cnt += (p[i] != 0.f);
    } else {
        const int* p = (const int*)mask + base;
        for (int i = lane; i < 512; i += 32) cnt += (p[i] != 0);
    }
#pragma unroll
    for (int off = 16; off; off >>= 1) cnt += __shfl_xor_sync(FULL, cnt, off);
    const int len = cnt;
    const int mid = len >> 1;

    float logscaleF = 0.f;

    if (wid == 2) {
        // ---- gold path ----
        float g = 0.f;
        for (int s = lane; s < len; s += 32)
            g += logf(g_expem[(base + s) * 37 + lab[s]]);
        for (int s = 1 + lane; s < len; s += 32)
            g += trans[lab[s - 1] * 37 + lab[s]];
        if (lane == 0) g += startt[lab[0]] + endt[lab[len - 1]];
#pragma unroll
        for (int off = 16; off; off >>= 1) g += __shfl_xor_sync(FULL, g, off);
        if (lane == 0) gp_s = g;
    } else if (wid == 0) {
        // ---- forward alpha: steps s = 1..mid ----
        const int t = lane;
        const bool hi = (t < 5);
        u64 EPL[19], EPH[19];
#pragma unroll 1
        for (int i = 0; i < 19; i++) {
            int i0 = 2 * i, i1 = 2 * i + 1;
            float eL0 = expf(trans[i0 * 37 + t]);
            float eL1 = (i1 < 37) ? expf(trans[i1 * 37 + t]) : 0.f;
            EPL[i] = pack2(eL0, eL1);
            float eH0 = hi ? expf(trans[i0 * 37 + t + 32]) : 0.f;
            float eH1 = (hi && i1 < 37) ? expf(trans[i1 * 37 + t + 32]) : 0.f;
            EPH[i] = pack2(eH0, eH1);
        }
        const float* empL = g_expem + base * 37 + t;
        const float* empH = g_expem + base * 37 + (hi ? t + 32 : 36);

        sa[0][t] = expf(startt[t]) * empL[0];
        sa[0][t + 32] = (hi ? expf(startt[t + 32]) : 0.f) * empH[0];
        sa[1][t + 32] = 0.f;
        __syncwarp();

        float curL[8], nxtL[8], curH[8], nxtH[8];
#pragma unroll
        for (int u = 0; u < 8; u++) {
            curL[u] = empL[(1 + u) * 37];
            nxtL[u] = empL[(9 + u) * 37];
            curH[u] = empH[(1 + u) * 37];
            nxtH[u] = empH[(9 + u) * 37];
        }

        const int Gf = mid >> 3;
        float naL = 0.f, naH = 0.f;
        int s = 1;
#pragma unroll 1
        for (int g = 0; g < Gf; g++) {
#pragma unroll
            for (int u = 0; u < 8; u++) {
                const float* buf = sa[u & 1];
                u64 L0 = 0ull, L1 = 0ull, H0 = 0ull, H1 = 0ull;
#pragma unroll
                for (int i = 0; i < 19; i++) {
                    u64 v = *(const u64*)&buf[2 * i];
                    if (i & 1) { L1 = fma2(v, EPL[i], L1); H1 = fma2(v, EPH[i], H1); }
                    else       { L0 = fma2(v, EPL[i], L0); H0 = fma2(v, EPH[i], H0); }
                }
                float l0, l1, h0, h1;
                unpack2(add2(L0, L1), l0, l1);
                unpack2(add2(H0, H1), h0, h1);
                naL = (l0 + l1) * curL[u];
                naH = (h0 + h1) * curH[u];
                if (u == 7) {
                    float scale = buf[0];
                    logscaleF += logf(scale);
                    float inv = 1.f / scale;
                    naL *= inv; naH *= inv;
                }
                float* wb = sa[(u + 1) & 1];
                wb[t] = naL;
                wb[t + 32] = naH;
                __syncwarp();
            }
            int sbase = s + 16;
#pragma unroll
            for (int u = 0; u < 8; u++) {
                curL[u] = nxtL[u]; curH[u] = nxtH[u];
                int ss = sbase + u; ss = (ss < 512) ? ss : 511;
                nxtL[u] = empL[ss * 37]; nxtH[u] = empH[ss * 37];
            }
            s += 8;
        }
#pragma unroll 1
        for (int u = 0; s <= mid; s++, u++) {
            const float* buf = sa[(s - 1) & 1];
            u64 L0 = 0ull, L1 = 0ull, H0 = 0ull, H1 = 0ull;
#pragma unroll
            for (int i = 0; i < 19; i++) {
                u64 v = *(const u64*)&buf[2 * i];
                if (i & 1) { L1 = fma2(v, EPL[i], L1); H1 = fma2(v, EPH[i], H1); }
                else       { L0 = fma2(v, EPL[i], L0); H0 = fma2(v, EPH[i], H0); }
            }
            float l0, l1, h0, h1;
            unpack2(add2(L0, L1), l0, l1);
            unpack2(add2(H0, H1), h0, h1);
            naL = (l0 + l1) * curL[u];
            naH = (h0 + h1) * curH[u];
            float* wb = sa[s & 1];
            wb[t] = naL;
            wb[t + 32] = naH;
            __syncwarp();
        }
    } else {
        // ---- backward g = em*beta: steps v = 0..V-1, s = len-2-v down to mid ----
        const int t = lane;
        const bool hi = (t < 5);
        u64 EPL[19], EPH[19];   // rows t and t+32 of E
#pragma unroll 1
        for (int i = 0; i < 19; i++) {
            int i0 = 2 * i, i1 = 2 * i + 1;
            float eL0 = expf(trans[t * 37 + i0]);
            float eL1 = (i1 < 37) ? expf(trans[t * 37 + i1]) : 0.f;
            EPL[i] = pack2(eL0, eL1);
            float eH0 = hi ? expf(trans[(t + 32) * 37 + i0]) : 0.f;
            float eH1 = (hi && i1 < 37) ? expf(trans[(t + 32) * 37 + i1]) : 0.f;
            EPH[i] = pack2(eH0, eH1);
        }
        const float* empL = g_expem + base * 37 + t;
        const float* empH = g_expem + base * 37 + (hi ? t + 32 : 36);

        sb[0][t] = empL[(size_t)(len - 1) * 37] * expf(endt[t]);
        sb[0][t + 32] = hi ? empH[(size_t)(len - 1) * 37] * expf(endt[t + 32]) : 0.f;
        sb[1][t + 32] = 0.f;
        __syncwarp();

        float curL[8], nxtL[8], curH[8], nxtH[8];
#pragma unroll
        for (int u = 0; u < 8; u++) {
            curL[u] = empL[(len - 2 - u) * 37];
            nxtL[u] = empL[(len - 10 - u) * 37];
            curH[u] = empH[(len - 2 - u) * 37];
            nxtH[u] = empH[(len - 10 - u) * 37];
        }

        const int V = len - 1 - mid;
        const int Gb = V >> 3;
        float naL = 0.f, naH = 0.f;
        float logscaleB = 0.f;
        int nb = len - 18;
        int v = 0;
#pragma unroll 1
        for (int g = 0; g < Gb; g++) {
#pragma unroll
            for (int u = 0; u < 8; u++) {
                const float* buf = sb[u & 1];
                u64 L0 = 0ull, L1 = 0ull, H0 = 0ull, H1 = 0ull;
#pragma unroll
                for (int i = 0; i < 19; i++) {
                    u64 w = *(const u64*)&buf[2 * i];
                    if (i & 1) { L1 = fma2(w, EPL[i], L1); H1 = fma2(w, EPH[i], H1); }
                    else       { L0 = fma2(w, EPL[i], L0); H0 = fma2(w, EPH[i], H0); }
                }
                float l0, l1, h0, h1;
                unpack2(add2(L0, L1), l0, l1);
                unpack2(add2(H0, H1), h0, h1);
                naL = (l0 + l1) * curL[u];
                naH = (h0 + h1) * curH[u];
                if (u == 7) {
                    float scale = buf[0];
                    logscaleB += logf(scale);
                    float inv = 1.f / scale;
                    naL *= inv; naH *= inv;
                }
                float* wb = sb[(u + 1) & 1];
                wb[t] = naL;
                wb[t + 32] = naH;
                __syncwarp();
            }
#pragma unroll
            for (int u = 0; u < 8; u++) {
                curL[u] = nxtL[u]; curH[u] = nxtH[u];
                int ss = nb - u; ss = (ss > 0) ? ss : 0;
                nxtL[u] = empL[ss * 37]; nxtH[u] = empH[ss * 37];
            }
            nb -= 8;
            v += 8;
        }
#pragma unroll 1
        for (int u = 0; v < V; v++, u++) {
            const float* buf = sb[v & 1];
            u64 L0 = 0ull, L1 = 0ull, H0 = 0ull, H1 = 0ull;
#pragma unroll
            for (int i = 0; i < 19; i++) {
                u64 w = *(const u64*)&buf[2 * i];
                if (i & 1) { L1 = fma2(w, EPL[i], L1); H1 = fma2(w, EPH[i], H1); }
                else       { L0 = fma2(w, EPL[i], L0); H0 = fma2(w, EPH[i], H0); }
            }
            float l0, l1, h0, h1;
            unpack2(add2(L0, L1), l0, l1);
            unpack2(add2(H0, H1), h0, h1);
            naL = (l0 + l1) * curL[u];
            naH = (h0 + h1) * curH[u];
            float* wb = sb[(v + 1) & 1];
            wb[t] = naL;
            wb[t + 32] = naH;
            __syncwarp();
        }
        if (lane == 0) lsB_s = logscaleB;
    }
    __syncthreads();

    // ---- combine in warp0: Z = sum alpha_mid * g_mid / em_mid ----
    if (wid == 0) {
        const int t = lane;
        const bool hi = (t < 5);
        const int V = len - 1 - mid;
        const float* am = sa[mid & 1];
        const float* gm = sb[V & 1];
        float emLm = g_expem[(base + mid) * 37 + t];
        float emHm = hi ? g_expem[(base + mid) * 37 + t + 32] : 1.f;
        float z = am[t] * gm[t] / emLm + (hi ? am[t + 32] * gm[t + 32] / emHm : 0.f);
#pragma unroll
        for (int off = 16; off; off >>= 1) z += __shfl_xor_sync(FULL, z, off);
        if (t == 0) g_partial[b] = logscaleF + lsB_s + logf(z) - gp_s;
    }
}

// ---------------- finalize: mean over batches ----------------
__global__ void finalize_kernel(float* __restrict__ out) {
    const int t = threadIdx.x;
    float v = g_partial[t] + g_partial[t + 32];
#pragma unroll
    for (int off = 16; off; off >>= 1) v += __shfl_xor_sync(0xffffffffu, v, off);
    if (t == 0) out[0] = v * (1.f / 64.f);
}

// ---------------- launch ----------------
extern "C" void kernel_launch(void* const* d_in, const int* in_sizes, int n_in,
                              void* d_out, int out_size) {
    const float* X      = (const float*)d_in[0];
    const void*  mask   = d_in[1];
    const int*   labels = (const int*)d_in[2];
    const float* W1     = (const float*)d_in[3];
    const float* b1     = (const float*)d_in[4];
    const float* W2     = (const float*)d_in[5];
    const float* b2     = (const float*)d_in[6];
    const float* trans  = (const float*)d_in[7];
    const float* startt = (const float*)d_in[8];
    const float* endt   = (const float*)d_in[9];
    float* out = (float*)d_out;

    static bool attr_done = false;
    if (!attr_done) {
        cudaFuncSetAttribute(gemm1_kernel,
                             cudaFuncAttributeMaxDynamicSharedMemorySize, G1_SMEM);
        attr_done = true;
    }

    gemm1_kernel<<<256, 256, G1_SMEM>>>(X, W1, b1);
    gemm2_kernel<<<256, 128>>>(W2, b2);
    crf_kernel<<<64, 96>>>(trans, startt, endt, labels, mask);
    finalize_kernel<<<1, 32>>>(out);
}

// round 12
// speedup vs baseline: 2.5005x; 1.0462x over previous
#include <cuda_runtime.h>
#include <cuda_bf16.h>
#include <cstdint>
#include <cstddef>

// Shapes: B=64, S=512, D=768, H=512, T=37. Output: scalar f32 loss.

// ---------------- device scratch (no runtime allocation) ----------------
__device__ __align__(16) __nv_bfloat16 g_h[(size_t)32768 * 512];   // 32 MB hidden
__device__ __align__(16) float g_expem[(size_t)32768 * 37];        // exp(logits)
__device__ float g_partial[64];

typedef unsigned long long u64;

// ---------------- helpers ----------------
__device__ __forceinline__ void mma16816(float* d, const unsigned* a, const unsigned* b) {
    asm volatile(
        "mma.sync.aligned.m16n8k16.row.col.f32.bf16.bf16.f32 "
        "{%0,%1,%2,%3},{%4,%5,%6,%7},{%8,%9},{%0,%1,%2,%3};\n"
        : "+f"(d[0]), "+f"(d[1]), "+f"(d[2]), "+f"(d[3])
        : "r"(a[0]), "r"(a[1]), "r"(a[2]), "r"(a[3]), "r"(b[0]), "r"(b[1]));
}

__device__ __forceinline__ void ldsm_x4(unsigned& r0, unsigned& r1, unsigned& r2,
                                        unsigned& r3, uint32_t addr) {
    asm volatile("ldmatrix.sync.aligned.m8n8.x4.shared.b16 {%0,%1,%2,%3}, [%4];"
                 : "=r"(r0), "=r"(r1), "=r"(r2), "=r"(r3) : "r"(addr));
}

__device__ __forceinline__ uint32_t smem_u32(const void* p) {
    uint32_t a;
    asm("{ .reg .u64 t; cvta.to.shared.u64 t, %1; cvt.u32.u64 %0, t; }" : "=r"(a) : "l"(p));
    return a;
}

__device__ __forceinline__ uint2 pack_bf16x4(float a, float b, float c, float d) {
    __nv_bfloat162 h0 = __floats2bfloat162_rn(a, b);
    __nv_bfloat162 h1 = __floats2bfloat162_rn(c, d);
    uint2 r;
    r.x = *reinterpret_cast<unsigned*>(&h0);
    r.y = *reinterpret_cast<unsigned*>(&h1);
    return r;
}

__device__ __forceinline__ u64 pack2(float lo, float hi) {
    u64 v; asm("mov.b64 %0, {%1, %2};" : "=l"(v) : "f"(lo), "f"(hi)); return v;
}
__device__ __forceinline__ void unpack2(u64 v, float& lo, float& hi) {
    asm("mov.b64 {%0, %1}, %2;" : "=f"(lo), "=f"(hi) : "l"(v));
}
__device__ __forceinline__ u64 fma2(u64 a, u64 b, u64 c) {
    u64 d; asm("fma.rn.f32x2 %0, %1, %2, %3;" : "=l"(d) : "l"(a), "l"(b), "l"(c)); return d;
}
__device__ __forceinline__ u64 add2(u64 a, u64 b) {
    u64 d; asm("add.rn.f32x2 %0, %1, %2;" : "=l"(d) : "l"(a), "l"(b)); return d;
}

// ---------------- GEMM1: h = relu(X@W1 + b1), bf16 mma + LDSM ----------------
#define AS_STRIDE 776
#define BS_STRIDE 40
#define BS_TILE   (128 * BS_STRIDE)
#define G1_SMEM ((128 * AS_STRIDE + 2 * BS_TILE) * 2)
__global__ __launch_bounds__(256) void gemm1_kernel(const float* __restrict__ X,
                                                    const float* __restrict__ W1,
                                                    const float* __restrict__ b1,
                                                    int mtile0) {
    extern __shared__ __nv_bfloat16 smem[];
    __nv_bfloat16* As  = smem;                    // [128][776]
    __nv_bfloat16* Bsb = smem + 128 * AS_STRIDE;  // 2 x [128][40]
    const int tid  = threadIdx.x;
    const int lane = tid & 31;
    const int wid  = tid >> 5;
    const int wm   = wid & 3;
    const int wn   = wid >> 2;
    const int m0   = (mtile0 + blockIdx.x) * 128;
    const int wrow = wm * 32;
    const int wcol = wn * 64;
    const int gp   = lane >> 2;
    const int tg   = lane & 3;
    const int nc   = tid & 127;
    const int kgb  = (tid >> 7) * 4;

    const uint32_t as_u32 = smem_u32(As);
    const uint32_t bs_u32 = as_u32 + 128 * AS_STRIDE * 2;
    const int rowA  = wrow + (lane & 7) + ((lane >> 3) & 1) * 8;
    const int kaddA = ((lane >> 4) & 1) * 8;
    const uint32_t aoff = as_u32 + (uint32_t)(rowA * AS_STRIDE + kaddA) * 2;
    const int rowB  = wcol + (lane & 7) + ((lane >> 4) & 1) * 8;
    const int kaddB = ((lane >> 3) & 1) * 8;
    const uint32_t boff = (uint32_t)(rowB * BS_STRIDE + kaddB) * 2;

#pragma unroll 4
    for (int i = 0; i < 96; i++) {
        int idx = tid + i * 256;
        int r = idx / 192, c = idx % 192;
        float4 v = *(const float4*)(X + (size_t)(m0 + r) * 768 + c * 4);
        *(uint2*)&As[r * AS_STRIDE + c * 4] = pack_bf16x4(v.x, v.y, v.z, v.w);
    }
    __syncthreads();

    for (int nt = 0; nt < 4; nt++) {
        const int n0 = nt * 128;

        float acc[2][8][4];
#pragma unroll
        for (int i = 0; i < 2; i++)
#pragma unroll
            for (int j = 0; j < 8; j++)
#pragma unroll
                for (int k = 0; k < 4; k++) acc[i][j][k] = 0.f;

        float rb[4][4];
#pragma unroll
        for (int i = 0; i < 4; i++) {
            int kr = kgb + i * 8;
#pragma unroll
            for (int j = 0; j < 4; j++)
                rb[i][j] = W1[(size_t)(kr + j) * 512 + n0 + nc];
        }
#pragma unroll
        for (int i = 0; i < 4; i++) {
            int kr = kgb + i * 8;
            *(uint2*)&Bsb[nc * BS_STRIDE + kr] =
                pack_bf16x4(rb[i][0], rb[i][1], rb[i][2], rb[i][3]);
        }
#pragma unroll
        for (int i = 0; i < 4; i++) {
            int kr = 32 + kgb + i * 8;
#pragma unroll
            for (int j = 0; j < 4; j++)
                rb[i][j] = W1[(size_t)(kr + j) * 512 + n0 + nc];
        }
        __syncthreads();

        for (int kt = 0; kt < 24; kt++) {
            if (kt < 23) {
                __nv_bfloat16* Bw = Bsb + ((kt + 1) & 1) * BS_TILE;
#pragma unroll
                for (int i = 0; i < 4; i++) {
                    int kr = kgb + i * 8;
                    *(uint2*)&Bw[nc * BS_STRIDE + kr] =
                        pack_bf16x4(rb[i][0], rb[i][1], rb[i][2], rb[i][3]);
                }
            }
            if (kt < 22) {
                int k0 = (kt + 2) * 32;
#pragma unroll
                for (int i = 0; i < 4; i++) {
                    int kr = k0 + kgb + i * 8;
#pragma unroll
                    for (int j = 0; j < 4; j++)
                        rb[i][j] = W1[(size_t)(kr + j) * 512 + n0 + nc];
                }
            }
            const uint32_t bbase = bs_u32 + (uint32_t)((kt & 1) * BS_TILE * 2) + boff;
            const int kbase = kt * 32;
#pragma unroll
            for (int kk = 0; kk < 32; kk += 16) {
                const uint32_t ka2 = (uint32_t)(kbase + kk) * 2;
                unsigned af[2][4], bfr[8][2];
                ldsm_x4(af[0][0], af[0][1], af[0][2], af[0][3], aoff + ka2);
                ldsm_x4(af[1][0], af[1][1], af[1][2], af[1][3],
                        aoff + 16 * AS_STRIDE * 2 + ka2);
                const uint32_t bb = bbase + (uint32_t)kk * 2;
#pragma unroll
                for (int j2 = 0; j2 < 4; j2++)
                    ldsm_x4(bfr[2 * j2][0], bfr[2 * j2][1],
                            bfr[2 * j2 + 1][0], bfr[2 * j2 + 1][1],
                            bb + (uint32_t)(j2 * 16 * BS_STRIDE) * 2);
#pragma unroll
                for (int i = 0; i < 2; i++)
#pragma unroll
                    for (int j = 0; j < 8; j++) mma16816(acc[i][j], af[i], bfr[j]);
            }
            __syncthreads();
        }

#pragma unroll
        for (int i = 0; i < 2; i++) {
            int r0 = m0 + wrow + i * 16 + gp;
            int r1 = r0 + 8;
#pragma unroll
            for (int j = 0; j < 8; j++) {
                int c = n0 + wcol + j * 8 + tg * 2;
                float bia0 = b1[c], bia1 = b1[c + 1];
                float v00 = fmaxf(acc[i][j][0] + bia0, 0.f);
                float v01 = fmaxf(acc[i][j][1] + bia1, 0.f);
                float v10 = fmaxf(acc[i][j][2] + bia0, 0.f);
                float v11 = fmaxf(acc[i][j][3] + bia1, 0.f);
                __nv_bfloat162 o0 = __floats2bfloat162_rn(v00, v01);
                __nv_bfloat162 o1 = __floats2bfloat162_rn(v10, v11);
                *(__nv_bfloat162*)&g_h[(size_t)r0 * 512 + c] = o0;
                *(__nv_bfloat162*)&g_h[(size_t)r1 * 512 + c] = o1;
            }
        }
        __syncthreads();
    }
}

// ---------------- GEMM2: expem = exp(h@W2 + b2) ----------------
__global__ __launch_bounds__(128) void gemm2_kernel(const float* __restrict__ W2,
                                                    const float* __restrict__ b2,
                                                    int mtile0) {
    __shared__ __nv_bfloat16 As[128 * 72];
    __shared__ __nv_bfloat16 Bs[40 * 72];
    const int tid  = threadIdx.x;
    const int lane = tid & 31;
    const int wid  = tid >> 5;
    const int m0   = (mtile0 + blockIdx.x) * 128;
    const int wrow = wid * 32;
    const int gp   = lane >> 2;
    const int tg   = lane & 3;

    float acc[2][5][4];
#pragma unroll
    for (int i = 0; i < 2; i++)
#pragma unroll
        for (int j = 0; j < 5; j++)
#pragma unroll
            for (int k = 0; k < 4; k++) acc[i][j][k] = 0.f;

    for (int kt = 0; kt < 8; kt++) {
        __syncthreads();
        int k0 = kt * 64;
#pragma unroll
        for (int i = 0; i < 16; i++) {
            int idx = tid + i * 128;
            int r = idx >> 4, c = idx & 15;
            *(uint2*)&As[r * 72 + c * 4] =
                *(const uint2*)&g_h[(size_t)(m0 + r) * 512 + k0 + c * 4];
        }
        for (int idx = tid; idx < 40 * 64; idx += 128) {
            int k = idx & 63, n = idx >> 6;
            Bs[n * 72 + k] = (n < 37) ? __float2bfloat16(W2[(size_t)(k0 + k) * 37 + n])
                                      : __float2bfloat16(0.f);
        }
        __syncthreads();
#pragma unroll
        for (int kk = 0; kk < 64; kk += 16) {
            unsigned af[2][4], bfr[5][2];
#pragma unroll
            for (int i = 0; i < 2; i++) {
                int r = wrow + i * 16 + gp;
                af[i][0] = *(const unsigned*)&As[r * 72 + kk + tg * 2];
                af[i][1] = *(const unsigned*)&As[(r + 8) * 72 + kk + tg * 2];
                af[i][2] = *(const unsigned*)&As[r * 72 + kk + tg * 2 + 8];
                af[i][3] = *(const unsigned*)&As[(r + 8) * 72 + kk + tg * 2 + 8];
            }
#pragma unroll
            for (int j = 0; j < 5; j++) {
                int n = j * 8 + gp;
                bfr[j][0] = *(const unsigned*)&Bs[n * 72 + kk + tg * 2];
                bfr[j][1] = *(const unsigned*)&Bs[n * 72 + kk + tg * 2 + 8];
            }
#pragma unroll
            for (int i = 0; i < 2; i++)
#pragma unroll
                for (int j = 0; j < 5; j++) mma16816(acc[i][j], af[i], bfr[j]);
        }
    }

#pragma unroll
    for (int i = 0; i < 2; i++) {
        int r0 = m0 + wrow + i * 16 + gp;
        int r1 = r0 + 8;
#pragma unroll
        for (int j = 0; j < 5; j++) {
            int c = j * 8 + tg * 2;
            if (c < 37) {
                float bia = b2[c];
                g_expem[(size_t)r0 * 37 + c] = expf(acc[i][j][0] + bia);
                g_expem[(size_t)r1 * 37 + c] = expf(acc[i][j][2] + bia);
            }
            if (c + 1 < 37) {
                float bia = b2[c + 1];
                g_expem[(size_t)r0 * 37 + c + 1] = expf(acc[i][j][1] + bia);
                g_expem[(size_t)r1 * 37 + c + 1] = expf(acc[i][j][3] + bia);
            }
        }
    }
}

// ---------------- CRF: forward/backward split (R11, + batch offset) ----------------
__global__ __launch_bounds__(96) void crf_kernel(const float* __restrict__ trans,
                                                 const float* __restrict__ startt,
                                                 const float* __restrict__ endt,
                                                 const int* __restrict__ labels,
                                                 const void* __restrict__ mask,
                                                 int b0) {
    __shared__ __align__(16) float sa[2][64];
    __shared__ __align__(16) float sb[2][64];
    __shared__ float gp_s, lsB_s;
    const int b = b0 + blockIdx.x, tid = threadIdx.x;
    const int lane = tid & 31;
    const int wid  = tid >> 5;
    const unsigned FULL = 0xffffffffu;
    const size_t base = (size_t)b * 512;
    const int* lab = labels + base;

    int cnt = 0;
    const unsigned w0 = *(const unsigned*)mask;
    if (w0 == 0x01010101u) {
        const uint4* p = (const uint4*)((const unsigned char*)mask + base);
        uint4 v = p[lane];
        cnt = __popc(v.x & 0x01010101u) + __popc(v.y & 0x01010101u) +
              __popc(v.z & 0x01010101u) + __popc(v.w & 0x01010101u);
    } else if (w0 == 0x3F800000u) {
        const float* p = (const float*)mask + base;
        for (int i = lane; i < 512; i += 32) cnt += (p[i] != 0.f);
    } else {
        const int* p = (const int*)mask + base;
        for (int i = lane; i < 512; i += 32) cnt += (p[i] != 0);
    }
#pragma unroll
    for (int off = 16; off; off >>= 1) cnt += __shfl_xor_sync(FULL, cnt, off);
    const int len = cnt;
    const int mid = len >> 1;

    float logscaleF = 0.f;

    if (wid == 2) {
        float g = 0.f;
        for (int s = lane; s < len; s += 32)
            g += logf(g_expem[(base + s) * 37 + lab[s]]);
        for (int s = 1 + lane; s < len; s += 32)
            g += trans[lab[s - 1] * 37 + lab[s]];
        if (lane == 0) g += startt[lab[0]] + endt[lab[len - 1]];
#pragma unroll
        for (int off = 16; off; off >>= 1) g += __shfl_xor_sync(FULL, g, off);
        if (lane == 0) gp_s = g;
    } else if (wid == 0) {
        const int t = lane;
        const bool hi = (t < 5);
        u64 EPL[19], EPH[19];
#pragma unroll 1
        for (int i = 0; i < 19; i++) {
            int i0 = 2 * i, i1 = 2 * i + 1;
            float eL0 = expf(trans[i0 * 37 + t]);
            float eL1 = (i1 < 37) ? expf(trans[i1 * 37 + t]) : 0.f;
            EPL[i] = pack2(eL0, eL1);
            float eH0 = hi ? expf(trans[i0 * 37 + t + 32]) : 0.f;
            float eH1 = (hi && i1 < 37) ? expf(trans[i1 * 37 + t + 32]) : 0.f;
            EPH[i] = pack2(eH0, eH1);
        }
        const float* empL = g_expem + base * 37 + t;
        const float* empH = g_expem + base * 37 + (hi ? t + 32 : 36);

        sa[0][t] = expf(startt[t]) * empL[0];
        sa[0][t + 32] = (hi ? expf(startt[t + 32]) : 0.f) * empH[0];
        sa[1][t + 32] = 0.f;
        __syncwarp();

        float curL[8], nxtL[8], curH[8], nxtH[8];
#pragma unroll
        for (int u = 0; u < 8; u++) {
            curL[u] = empL[(1 + u) * 37];
            nxtL[u] = empL[(9 + u) * 37];
            curH[u] = empH[(1 + u) * 37];
            nxtH[u] = empH[(9 + u) * 37];
        }

        const int Gf = mid >> 3;
        float naL = 0.f, naH = 0.f;
        int s = 1;
#pragma unroll 1
        for (int g = 0; g < Gf; g++) {
#pragma unroll
            for (int u = 0; u < 8; u++) {
                const float* buf = sa[u & 1];
                u64 L0 = 0ull, L1 = 0ull, H0 = 0ull, H1 = 0ull;
#pragma unroll
                for (int i = 0; i < 19; i++) {
                    u64 v = *(const u64*)&buf[2 * i];
                    if (i & 1) { L1 = fma2(v, EPL[i], L1); H1 = fma2(v, EPH[i], H1); }
                    else       { L0 = fma2(v, EPL[i], L0); H0 = fma2(v, EPH[i], H0); }
                }
                float l0, l1, h0, h1;
                unpack2(add2(L0, L1), l0, l1);
                unpack2(add2(H0, H1), h0, h1);
                naL = (l0 + l1) * curL[u];
                naH = (h0 + h1) * curH[u];
                if (u == 7) {
                    float scale = buf[0];
                    logscaleF += logf(scale);
                    float inv = 1.f / scale;
                    naL *= inv; naH *= inv;
                }
                float* wb = sa[(u + 1) & 1];
                wb[t] = naL;
                wb[t + 32] = naH;
                __syncwarp();
            }
            int sbase = s + 16;
#pragma unroll
            for (int u = 0; u < 8; u++) {
                curL[u] = nxtL[u]; curH[u] = nxtH[u];
                int ss = sbase + u; ss = (ss < 512) ? ss : 511;
                nxtL[u] = empL[ss * 37]; nxtH[u] = empH[ss * 37];
            }
            s += 8;
        }
#pragma unroll 1
        for (int u = 0; s <= mid; s++, u++) {
            const float* buf = sa[(s - 1) & 1];
            u64 L0 = 0ull, L1 = 0ull, H0 = 0ull, H1 = 0ull;
#pragma unroll
            for (int i = 0; i < 19; i++) {
                u64 v = *(const u64*)&buf[2 * i];
                if (i & 1) { L1 = fma2(v, EPL[i], L1); H1 = fma2(v, EPH[i], H1); }
                else       { L0 = fma2(v, EPL[i], L0); H0 = fma2(v, EPH[i], H0); }
            }
            float l0, l1, h0, h1;
            unpack2(add2(L0, L1), l0, l1);
            unpack2(add2(H0, H1), h0, h1);
            naL = (l0 + l1) * curL[u];
            naH = (h0 + h1) * curH[u];
            float* wb = sa[s & 1];
            wb[t] = naL;
            wb[t + 32] = naH;
            __syncwarp();
        }
    } else {
        const int t = lane;
        const bool hi = (t < 5);
        u64 EPL[19], EPH[19];
#pragma unroll 1
        for (int i = 0; i < 19; i++) {
            int i0 = 2 * i, i1 = 2 * i + 1;
            float eL0 = expf(trans[t * 37 + i0]);
            float eL1 = (i1 < 37) ? expf(trans[t * 37 + i1]) : 0.f;
            EPL[i] = pack2(eL0, eL1);
            float eH0 = hi ? expf(trans[(t + 32) * 37 + i0]) : 0.f;
            float eH1 = (hi && i1 < 37) ? expf(trans[(t + 32) * 37 + i1]) : 0.f;
            EPH[i] = pack2(eH0, eH1);
        }
        const float* empL = g_expem + base * 37 + t;
        const float* empH = g_expem + base * 37 + (hi ? t + 32 : 36);

        sb[0][t] = empL[(size_t)(len - 1) * 37] * expf(endt[t]);
        sb[0][t + 32] = hi ? empH[(size_t)(len - 1) * 37] * expf(endt[t + 32]) : 0.f;
        sb[1][t + 32] = 0.f;
        __syncwarp();

        float curL[8], nxtL[8], curH[8], nxtH[8];
#pragma unroll
        for (int u = 0; u < 8; u++) {
            curL[u] = empL[(len - 2 - u) * 37];
            nxtL[u] = empL[(len - 10 - u) * 37];
            curH[u] = empH[(len - 2 - u) * 37];
            nxtH[u] = empH[(len - 10 - u) * 37];
        }

        const int V = len - 1 - mid;
        const int Gb = V >> 3;
        float naL = 0.f, naH = 0.f;
        float logscaleB = 0.f;
        int nb = len - 18;
        int v = 0;
#pragma unroll 1
        for (int g = 0; g < Gb; g++) {
#pragma unroll
            for (int u = 0; u < 8; u++) {
                const float* buf = sb[u & 1];
                u64 L0 = 0ull, L1 = 0ull, H0 = 0ull, H1 = 0ull;
#pragma unroll
                for (int i = 0; i < 19; i++) {
                    u64 w = *(const u64*)&buf[2 * i];
                    if (i & 1) { L1 = fma2(w, EPL[i], L1); H1 = fma2(w, EPH[i], H1); }
                    else       { L0 = fma2(w, EPL[i], L0); H0 = fma2(w, EPH[i], H0); }
                }
                float l0, l1, h0, h1;
                unpack2(add2(L0, L1), l0, l1);
                unpack2(add2(H0, H1), h0, h1);
                naL = (l0 + l1) * curL[u];
                naH = (h0 + h1) * curH[u];
                if (u == 7) {
                    float scale = buf[0];
                    logscaleB += logf(scale);
                    float inv = 1.f / scale;
                    naL *= inv; naH *= inv;
                }
                float* wb = sb[(u + 1) & 1];
                wb[t] = naL;
                wb[t + 32] = naH;
                __syncwarp();
            }
#pragma unroll
            for (int u = 0; u < 8; u++) {
                curL[u] = nxtL[u]; curH[u] = nxtH[u];
                int ss = nb - u; ss = (ss > 0) ? ss : 0;
                nxtL[u] = empL[ss * 37]; nxtH[u] = empH[ss * 37];
            }
            nb -= 8;
            v += 8;
        }
#pragma unroll 1
        for (int u = 0; v < V; v++, u++) {
            const float* buf = sb[v & 1];
            u64 L0 = 0ull, L1 = 0ull, H0 = 0ull, H1 = 0ull;
#pragma unroll
            for (int i = 0; i < 19; i++) {
                u64 w = *(const u64*)&buf[2 * i];
                if (i & 1) { L1 = fma2(w, EPL[i], L1); H1 = fma2(w, EPH[i], H1); }
                else       { L0 = fma2(w, EPL[i], L0); H0 = fma2(w, EPH[i], H0); }
            }
            float l0, l1, h0, h1;
            unpack2(add2(L0, L1), l0, l1);
            unpack2(add2(H0, H1), h0, h1);
            naL = (l0 + l1) * curL[u];
            naH = (h0 + h1) * curH[u];
            float* wb = sb[(v + 1) & 1];
            wb[t] = naL;
            wb[t + 32] = naH;
            __syncwarp();
        }
        if (lane == 0) lsB_s = logscaleB;
    }
    __syncthreads();

    if (wid == 0) {
        const int t = lane;
        const bool hi = (t < 5);
        const int V = len - 1 - mid;
        const float* am = sa[mid & 1];
        const float* gm = sb[V & 1];
        float emLm = g_expem[(base + mid) * 37 + t];
        float emHm = hi ? g_expem[(base + mid) * 37 + t + 32] : 1.f;
        float z = am[t] * gm[t] / emLm + (hi ? am[t + 32] * gm[t + 32] / emHm : 0.f);
#pragma unroll
        for (int off = 16; off; off >>= 1) z += __shfl_xor_sync(FULL, z, off);
        if (t == 0) g_partial[b] = logscaleF + lsB_s + logf(z) - gp_s;
    }
}

// ---------------- finalize: mean over batches ----------------
__global__ void finalize_kernel(float* __restrict__ out) {
    const int t = threadIdx.x;
    float v = g_partial[t] + g_partial[t + 32];
#pragma unroll
    for (int off = 16; off; off >>= 1) v += __shfl_xor_sync(0xffffffffu, v, off);
    if (t == 0) out[0] = v * (1.f / 64.f);
}

// ---------------- launch: 2-chunk pipeline across two streams ----------------
extern "C" void kernel_launch(void* const* d_in, const int* in_sizes, int n_in,
                              void* d_out, int out_size) {
    const float* X      = (const float*)d_in[0];
    const void*  mask   = d_in[1];
    const int*   labels = (const int*)d_in[2];
    const float* W1     = (const float*)d_in[3];
    const float* b1     = (const float*)d_in[4];
    const float* W2     = (const float*)d_in[5];
    const float* b2     = (const float*)d_in[6];
    const float* trans  = (const float*)d_in[7];
    const float* startt = (const float*)d_in[8];
    const float* endt   = (const float*)d_in[9];
    float* out = (float*)d_out;

    static cudaStream_t s1 = nullptr;
    static cudaEvent_t evA = nullptr, evB = nullptr;
    if (!s1) {
        cudaFuncSetAttribute(gemm1_kernel,
                             cudaFuncAttributeMaxDynamicSharedMemorySize, G1_SMEM);
        cudaStreamCreateWithFlags(&s1, cudaStreamNonBlocking);
        cudaEventCreateWithFlags(&evA, cudaEventDisableTiming);
        cudaEventCreateWithFlags(&evB, cudaEventDisableTiming);
    }

    // chunk 0: batches 0..31 (m-tiles 0..127); chunk 1: batches 32..63
    gemm1_kernel<<<128, 256, G1_SMEM>>>(X, W1, b1, 0);
    cudaEventRecord(evA, 0);
    gemm1_kernel<<<128, 256, G1_SMEM>>>(X, W1, b1, 128);   // default stream

    cudaStreamWaitEvent(s1, evA, 0);
    gemm2_kernel<<<128, 128, 0, s1>>>(W2, b2, 0);
    crf_kernel<<<32, 96, 0, s1>>>(trans, startt, endt, labels, mask, 0);
    cudaEventRecord(evB, s1);

    gemm2_kernel<<<128, 128>>>(W2, b2, 128);
    crf_kernel<<<32, 96>>>(trans, startt, endt, labels, mask, 32);
    cudaStreamWaitEvent(0, evB, 0);
    finalize_kernel<<<1, 32>>>(out);
}